// round 14
// baseline (speedup 1.0000x reference)
#include <cuda_runtime.h>
#include <cuda_bf16.h>
#include <mma.h>
#include <math.h>

using namespace nvcuda;

#define N_NODES_C 20000
#define N_EDGES_C 320000
#define NH 128
#define DIN 262
#define NLAYERS 3
#define BN_EPS 1e-5f
#define GRID_P 148

// ---------------- scratch ----------------
__device__ float g_x[N_NODES_C * NH];
__device__ float g_x2[N_NODES_C * NH];
__device__ float g_Y[(size_t)N_NODES_C * 256];              // [Y1 | Y2] per node
__device__ __nv_bfloat16 g_h[(size_t)N_EDGES_C * NH];       // hpre (bf16, slot order)
__device__ float g_s[N_EDGES_C];                            // per-slot phi_x scalar
__device__ float g_eap[N_EDGES_C * 4];                      // permuted edge_attr
__device__ int   g_colj[N_EDGES_C];                         // permuted col index
__device__ float g_stats[2 * NH];
__device__ int   g_cnt[N_NODES_C];
__device__ int   g_rowptr[N_NODES_C + 1];
__device__ int   g_eidx[N_EDGES_C];

__device__ __forceinline__ float psi_f(float z) {
    return copysignf(log1pf(fabsf(z)), z);
}
__device__ __forceinline__ float sigmoid_f(float z) {
    return 1.0f / (1.0f + expf(-z));
}
__device__ __forceinline__ __nv_bfloat16 bf(float x) { return __float2bfloat16(x); }

typedef wmma::fragment<wmma::matrix_a, 16, 16, 16, __nv_bfloat16, wmma::row_major> FragA;
typedef wmma::fragment<wmma::matrix_b, 16, 16, 16, __nv_bfloat16, wmma::row_major> FragB;
typedef wmma::fragment<wmma::accumulator, 16, 16, 16, float> FragC;

// ================= CSR build (once per launch) ========================================
__global__ void k_hist(const int* __restrict__ ei) {
    int e = blockIdx.x * 256 + threadIdx.x;
    if (e < N_EDGES_C) atomicAdd(&g_cnt[ei[e]], 1);
}

__global__ void k_scan() {
    __shared__ int part[1024];
    int t = threadIdx.x;
    int base = t * 20;
    int s = 0;
    for (int i = 0; i < 20; i++) {
        int idx = base + i;
        if (idx < N_NODES_C) s += g_cnt[idx];
    }
    part[t] = s;
    __syncthreads();
    for (int off = 1; off < 1024; off <<= 1) {
        int v = (t >= off) ? part[t - off] : 0;
        __syncthreads();
        part[t] += v;
        __syncthreads();
    }
    int run = (t == 0) ? 0 : part[t - 1];
    for (int i = 0; i < 20; i++) {
        int idx = base + i;
        if (idx <= N_NODES_C) g_rowptr[idx] = run;
        if (idx < N_NODES_C) run += g_cnt[idx];
    }
    for (int i = 0; i < 20; i++) {
        int idx = base + i;
        if (idx < N_NODES_C) g_cnt[idx] = 0;
    }
}

__global__ void k_fillcsr(const int* __restrict__ ei) {
    int e = blockIdx.x * 256 + threadIdx.x;
    if (e < N_EDGES_C) {
        int r = ei[e];
        int slot = g_rowptr[r] + atomicAdd(&g_cnt[r], 1);
        g_eidx[slot] = e;
    }
}

__global__ void k_sortseg() {
    int n = blockIdx.x * 256 + threadIdx.x;
    if (n >= N_NODES_C) return;
    int beg = g_rowptr[n], end = g_rowptr[n + 1];
    for (int i = beg + 1; i < end; i++) {
        int v = g_eidx[i], j = i - 1;
        while (j >= beg && g_eidx[j] > v) { g_eidx[j + 1] = g_eidx[j]; j--; }
        g_eidx[j + 1] = v;
    }
}

__global__ void k_perm(const int* __restrict__ ei, const float* __restrict__ ea) {
    int j = blockIdx.x * 256 + threadIdx.x;
    if (j < N_EDGES_C) {
        int e = g_eidx[j];
        g_colj[j] = ei[N_EDGES_C + e];
        *(float4*)&g_eap[(size_t)j * 4] = *(const float4*)&ea[(size_t)e * 4];
    }
}

// ================= node GEMM: Y = X @ [W1a | W1b] (2 CTAs/SM) =========================
__global__ void __launch_bounds__(256, 2)
k_node(const float* __restrict__ xin, const float* __restrict__ W1) {
    extern __shared__ __align__(16) char smraw[];
    __nv_bfloat16* Bs = (__nv_bfloat16*)smraw;        // 128 x 264
    __nv_bfloat16* As = Bs + 128 * 264;               // 64 x 136

    int tid = threadIdx.x;
    int warp = tid >> 5;
    int wy = warp >> 2, wx = warp & 3;

    for (int idx = tid; idx < 128 * 256; idx += 256) {
        int k = idx >> 8, c = idx & 255;
        float v = (c < 128) ? W1[(size_t)k * NH + c] : W1[(size_t)(128 + k) * NH + (c - 128)];
        Bs[k * 264 + c] = bf(v);
    }

    const int NT = (N_NODES_C + 63) / 64;   // 313
    for (int tile = blockIdx.x; tile < NT; tile += GRID_P * 2) {
        int n0 = tile * 64;
        __syncthreads();
        for (int idx = tid; idx < 64 * 32; idx += 256) {
            int e = idx >> 5, g = idx & 31;
            int r = n0 + e; if (r >= N_NODES_C) r = N_NODES_C - 1;
            float4 v = *(const float4*)&xin[(size_t)r * NH + g * 4];
            __nv_bfloat16* dst = &As[e * 136 + g * 4];
            dst[0] = bf(v.x); dst[1] = bf(v.y); dst[2] = bf(v.z); dst[3] = bf(v.w);
        }
        __syncthreads();

        FragC acc[2][4];
#pragma unroll
        for (int i = 0; i < 2; i++)
#pragma unroll
            for (int j = 0; j < 4; j++) wmma::fill_fragment(acc[i][j], 0.f);

#pragma unroll
        for (int kk = 0; kk < NH; kk += 16) {
            FragA a0, a1;
            wmma::load_matrix_sync(a0, &As[(wy * 32) * 136 + kk], 136);
            wmma::load_matrix_sync(a1, &As[(wy * 32 + 16) * 136 + kk], 136);
#pragma unroll
            for (int j = 0; j < 4; j++) {
                FragB bfr;
                wmma::load_matrix_sync(bfr, &Bs[kk * 264 + wx * 64 + j * 16], 264);
                wmma::mma_sync(acc[0][j], a0, bfr, acc[0][j]);
                wmma::mma_sync(acc[1][j], a1, bfr, acc[1][j]);
            }
        }
#pragma unroll
        for (int i = 0; i < 2; i++) {
            int row0 = n0 + wy * 32 + i * 16;
            if (row0 + 16 <= N_NODES_C) {
#pragma unroll
                for (int j = 0; j < 4; j++)
                    wmma::store_matrix_sync(&g_Y[(size_t)row0 * 256 + wx * 64 + j * 16],
                                            acc[i][j], 256, wmma::mem_row_major);
            }
        }
    }
}

// ================= stats pass: warp-per-node over CSR, 2-edge ILP =====================
__global__ void __launch_bounds__(256)
k_stats(const float* __restrict__ xin, const float* __restrict__ W1c) {
    __shared__ float w1c[6 * 128];
    __shared__ float red[2 * 128];

    int tid = threadIdx.x;
    int warp = tid >> 5, lane = tid & 31;
    for (int i = tid; i < 6 * 128; i += 256) w1c[i] = W1c[i];
    if (tid < 256) red[tid] = 0.f;
    __syncthreads();

    float acc_s[4] = {0.f, 0.f, 0.f, 0.f};
    float acc_q[4] = {0.f, 0.f, 0.f, 0.f};
    int col = lane * 4;
    float sgn0 = (lane == 0) ? 1.f : -1.f;

    int gw = blockIdx.x * 8 + warp;
    int tw = gridDim.x * 8;
    for (int n = gw; n < N_NODES_C; n += tw) {
        float4 xr = *(const float4*)&xin[(size_t)n * NH + col];
        float4 y1 = *(const float4*)&g_Y[(size_t)n * 256 + col];
        float hb[4] = {y1.x, y1.y, y1.z, y1.w};
        int beg = g_rowptr[n], end = g_rowptr[n + 1];
        int j = beg;

        // 2 edges per iteration: interleaved gathers + shuffle chains
        for (; j + 1 < end; j += 2) {
            int c0 = g_colj[j];
            int c1 = g_colj[j + 1];
            float4 xc0 = *(const float4*)&xin[(size_t)c0 * NH + col];
            float4 xc1 = *(const float4*)&xin[(size_t)c1 * NH + col];
            float4 y20 = *(const float4*)&g_Y[(size_t)c0 * 256 + 128 + col];
            float4 y21 = *(const float4*)&g_Y[(size_t)c1 * 256 + 128 + col];
            float4 ev0 = *(const float4*)&g_eap[(size_t)j * 4];
            float4 ev1 = *(const float4*)&g_eap[(size_t)(j + 1) * 4];

            float d0x = xr.x - xc0.x, d0y = xr.y - xc0.y, d0z = xr.z - xc0.z, d0w = xr.w - xc0.w;
            float d1x = xr.x - xc1.x, d1y = xr.y - xc1.y, d1z = xr.z - xc1.z, d1w = xr.w - xc1.w;
            float dd0 = sgn0 * d0x * d0x - d0y * d0y - d0z * d0z - d0w * d0w;
            float ij0 = sgn0 * xr.x * xc0.x - xr.y * xc0.y - xr.z * xc0.z - xr.w * xc0.w;
            float dd1 = sgn0 * d1x * d1x - d1y * d1y - d1z * d1z - d1w * d1w;
            float ij1 = sgn0 * xr.x * xc1.x - xr.y * xc1.y - xr.z * xc1.z - xr.w * xc1.w;
#pragma unroll
            for (int o = 16; o; o >>= 1) {
                dd0 += __shfl_xor_sync(0xffffffffu, dd0, o);
                ij0 += __shfl_xor_sync(0xffffffffu, ij0, o);
                dd1 += __shfl_xor_sync(0xffffffffu, dd1, o);
                ij1 += __shfl_xor_sync(0xffffffffu, ij1, o);
            }
            float nrm0 = psi_f(dd0), dt0 = psi_f(ij0);
            float nrm1 = psi_f(dd1), dt1 = psi_f(ij1);

            float hv0[4] = {hb[0] + y20.x, hb[1] + y20.y, hb[2] + y20.z, hb[3] + y20.w};
            float hv1[4] = {hb[0] + y21.x, hb[1] + y21.y, hb[2] + y21.z, hb[3] + y21.w};
            float ho0[4], ho1[4];
#pragma unroll
            for (int q = 0; q < 4; q++) {
                int cc = col + q;
                float w0 = w1c[cc], w1 = w1c[128 + cc], w2 = w1c[256 + cc];
                float w3 = w1c[384 + cc], w4 = w1c[512 + cc], w5 = w1c[640 + cc];
                float h0 = hv0[q], h1 = hv1[q];
                h0 = fmaf(ev0.x, w0, h0);  h1 = fmaf(ev1.x, w0, h1);
                h0 = fmaf(ev0.y, w1, h0);  h1 = fmaf(ev1.y, w1, h1);
                h0 = fmaf(ev0.z, w2, h0);  h1 = fmaf(ev1.z, w2, h1);
                h0 = fmaf(ev0.w, w3, h0);  h1 = fmaf(ev1.w, w3, h1);
                h0 = fmaf(nrm0, w4, h0);   h1 = fmaf(nrm1, w4, h1);
                h0 = fmaf(dt0, w5, h0);    h1 = fmaf(dt1, w5, h1);
                ho0[q] = h0; ho1[q] = h1;
                acc_s[q] += h0 + h1;
                acc_q[q] = fmaf(h0, h0, acc_q[q]);
                acc_q[q] = fmaf(h1, h1, acc_q[q]);
            }
            {
                __nv_bfloat162 a = __floats2bfloat162_rn(ho0[0], ho0[1]);
                __nv_bfloat162 b = __floats2bfloat162_rn(ho0[2], ho0[3]);
                uint2 pk; pk.x = *(unsigned int*)&a; pk.y = *(unsigned int*)&b;
                *(uint2*)&g_h[(size_t)j * NH + col] = pk;
            }
            {
                __nv_bfloat162 a = __floats2bfloat162_rn(ho1[0], ho1[1]);
                __nv_bfloat162 b = __floats2bfloat162_rn(ho1[2], ho1[3]);
                uint2 pk; pk.x = *(unsigned int*)&a; pk.y = *(unsigned int*)&b;
                *(uint2*)&g_h[(size_t)(j + 1) * NH + col] = pk;
            }
        }

        // tail edge
        if (j < end) {
            int c = g_colj[j];
            float4 xc = *(const float4*)&xin[(size_t)c * NH + col];
            float4 y2 = *(const float4*)&g_Y[(size_t)c * 256 + 128 + col];
            float dx = xr.x - xc.x, dy = xr.y - xc.y, dz = xr.z - xc.z, dw = xr.w - xc.w;
            float dd = sgn0 * dx * dx - dy * dy - dz * dz - dw * dw;
            float ij = sgn0 * xr.x * xc.x - xr.y * xc.y - xr.z * xc.z - xr.w * xc.w;
#pragma unroll
            for (int o = 16; o; o >>= 1) {
                dd += __shfl_xor_sync(0xffffffffu, dd, o);
                ij += __shfl_xor_sync(0xffffffffu, ij, o);
            }
            float nrm = psi_f(dd), dt = psi_f(ij);
            float4 eav = *(const float4*)&g_eap[(size_t)j * 4];
            float ho[4];
#pragma unroll
            for (int q = 0; q < 4; q++) {
                int cc = col + q;
                float h = hb[q] + ((const float*)&y2)[q];
                h = fmaf(eav.x, w1c[cc], h);
                h = fmaf(eav.y, w1c[128 + cc], h);
                h = fmaf(eav.z, w1c[256 + cc], h);
                h = fmaf(eav.w, w1c[384 + cc], h);
                h = fmaf(nrm, w1c[512 + cc], h);
                h = fmaf(dt, w1c[640 + cc], h);
                ho[q] = h;
                acc_s[q] += h;
                acc_q[q] = fmaf(h, h, acc_q[q]);
            }
            __nv_bfloat162 a = __floats2bfloat162_rn(ho[0], ho[1]);
            __nv_bfloat162 b = __floats2bfloat162_rn(ho[2], ho[3]);
            uint2 pk; pk.x = *(unsigned int*)&a; pk.y = *(unsigned int*)&b;
            *(uint2*)&g_h[(size_t)j * NH + col] = pk;
        }
    }
#pragma unroll
    for (int q = 0; q < 4; q++) {
        atomicAdd(&red[col + q], acc_s[q]);
        atomicAdd(&red[128 + col + q], acc_q[q]);
    }
    __syncthreads();
    if (tid < 256) atomicAdd(&g_stats[tid], red[tid]);
}

// ================= fused edge MLP: FOUR 4-warp pipelines, in-CTA BN finalize ==========
#define BARG() asm volatile("bar.sync %0, 128;" :: "r"(group + 1) : "memory")

__global__ void __launch_bounds__(512, 1)
k_fused(const float* __restrict__ gamma, const float* __restrict__ beta,
        const float* __restrict__ W2, const float* __restrict__ b2,
        const float* __restrict__ Wa, const float* __restrict__ ba,
        const float* __restrict__ Wb,
        const float* __restrict__ Wm, const float* __restrict__ bm) {
    extern __shared__ __align__(16) char smraw[];
    __nv_bfloat16* W2s = (__nv_bfloat16*)smraw;       // 128 x 136
    __nv_bfloat16* Was = W2s + 128 * 136;             // 128 x 136
    __nv_bfloat16* Sall = Was + 128 * 136;            // 4 x (32 x 136) bf16
    float* Sfall = (float*)(Sall + 4 * 32 * 136);     // 4 x (32 x 132) fp32
    float* p_bnA = Sfall + 4 * 32 * 132;
    float* p_bnB = p_bnA + NH;
    float* p_b2  = p_bnB + NH;
    float* p_ba  = p_b2 + NH;
    float* p_Wm  = p_ba + NH;
    float* p_Wb  = p_Wm + NH;
    float* wg_all = p_Wb + NH;                        // 4 x 32

    int tid = threadIdx.x;
    int warp = tid >> 5, lane = tid & 31;
    int group = warp >> 2;                 // 0..3
    int gwarp = warp & 3;                  // 0..3 (column quarter)
    float bmv = bm[0];

    __nv_bfloat16* S  = Sall + group * 32 * 136;
    float*         Sf = Sfall + group * 32 * 132;
    float*         wgv = wg_all + group * 32;

    for (int idx = tid; idx < NH * NH; idx += 512) {
        int k = idx >> 7, c = idx & 127;
        W2s[k * 136 + c] = bf(W2[idx]);
        Was[k * 136 + c] = bf(Wa[idx]);
    }
    if (tid < NH) {
        float inv = 1.f / (float)N_EDGES_C;
        float mean = g_stats[tid] * inv;
        float var = g_stats[NH + tid] * inv - mean * mean;
        float sc = gamma[tid] * rsqrtf(var + BN_EPS);
        p_bnA[tid] = sc;
        p_bnB[tid] = beta[tid] - mean * sc;
        p_b2[tid]  = b2[tid];
        p_ba[tid]  = ba[tid];
        p_Wm[tid]  = Wm[tid];
        p_Wb[tid]  = Wb[tid];
    }
    __syncthreads();

    const int NT = N_EDGES_C / 32;          // 10000
    int tid_g = tid & 127;
    int pe = tid_g >> 4, pg = tid_g & 15;

    int tile = blockIdx.x * 4 + group;
    uint4 pre[4];
    if (tile < NT) {
#pragma unroll
        for (int it = 0; it < 4; it++) {
            int e = pe + it * 8;
            pre[it] = *(const uint4*)&g_h[(size_t)(tile * 32 + e) * NH + pg * 8];
        }
    }

    for (; tile < NT; tile += GRID_P * 4) {
        int e0 = tile * 32;

        // phase 1: convert prefetched hpre; BN + ReLU -> S
#pragma unroll
        for (int it = 0; it < 4; it++) {
            int e = pe + it * 8;
            __nv_bfloat162* hp = (__nv_bfloat162*)&pre[it];
            int cc0 = pg * 8;
            uint4 outp;
            __nv_bfloat162* op = (__nv_bfloat162*)&outp;
#pragma unroll
            for (int q = 0; q < 4; q++) {
                float2 f = __bfloat1622float2(hp[q]);
                int c0 = cc0 + q * 2;
                float v0 = fmaxf(fmaf(f.x, p_bnA[c0 + 0], p_bnB[c0 + 0]), 0.f);
                float v1 = fmaxf(fmaf(f.y, p_bnA[c0 + 1], p_bnB[c0 + 1]), 0.f);
                op[q] = __floats2bfloat162_rn(v0, v1);
            }
            *(uint4*)&S[e * 136 + pg * 8] = outp;
        }
        {
            int ntile = tile + GRID_P * 4;
            if (ntile < NT) {
#pragma unroll
                for (int it = 0; it < 4; it++) {
                    int e = pe + it * 8;
                    pre[it] = *(const uint4*)&g_h[(size_t)(ntile * 32 + e) * NH + pg * 8];
                }
            }
        }
        BARG();

        // phase 2: Sf = S @ W2
        {
            FragC acc[2][2];
#pragma unroll
            for (int i = 0; i < 2; i++)
#pragma unroll
                for (int j = 0; j < 2; j++) wmma::fill_fragment(acc[i][j], 0.f);
#pragma unroll
            for (int kk = 0; kk < NH; kk += 16) {
                FragA a0, a1; FragB b0, b1;
                wmma::load_matrix_sync(a0, &S[0 * 136 + kk], 136);
                wmma::load_matrix_sync(a1, &S[16 * 136 + kk], 136);
                wmma::load_matrix_sync(b0, &W2s[kk * 136 + gwarp * 32], 136);
                wmma::load_matrix_sync(b1, &W2s[kk * 136 + gwarp * 32 + 16], 136);
                wmma::mma_sync(acc[0][0], a0, b0, acc[0][0]);
                wmma::mma_sync(acc[0][1], a0, b1, acc[0][1]);
                wmma::mma_sync(acc[1][0], a1, b0, acc[1][0]);
                wmma::mma_sync(acc[1][1], a1, b1, acc[1][1]);
            }
#pragma unroll
            for (int i = 0; i < 2; i++)
#pragma unroll
                for (int j = 0; j < 2; j++)
                    wmma::store_matrix_sync(&Sf[(i * 16) * 132 + gwarp * 32 + j * 16],
                                            acc[i][j], 132, wmma::mem_row_major);
        }
        BARG();

        // phase 3: bias + ReLU -> S; gate -> wgv
#pragma unroll
        for (int t = 0; t < 8; t++) {
            int e = gwarp * 8 + t;
            float v[4];
            float p = 0.f;
#pragma unroll
            for (int u = 0; u < 4; u++) {
                int c = lane + 32 * u;
                v[u] = fmaxf(Sf[e * 132 + c] + p_b2[c], 0.f);
                p = fmaf(v[u], p_Wm[c], p);
            }
#pragma unroll
            for (int o = 16; o; o >>= 1) p += __shfl_xor_sync(0xffffffffu, p, o);
            if (lane == 0) wgv[e] = sigmoid_f(p + bmv);
#pragma unroll
            for (int u = 0; u < 4; u++) {
                int c = lane + 32 * u;
                S[e * 136 + c] = bf(v[u]);
            }
        }
        BARG();

        // phase 4: Sf = S @ Wa
        {
            FragC acc[2][2];
#pragma unroll
            for (int i = 0; i < 2; i++)
#pragma unroll
                for (int j = 0; j < 2; j++) wmma::fill_fragment(acc[i][j], 0.f);
#pragma unroll
            for (int kk = 0; kk < NH; kk += 16) {
                FragA a0, a1; FragB b0, b1;
                wmma::load_matrix_sync(a0, &S[0 * 136 + kk], 136);
                wmma::load_matrix_sync(a1, &S[16 * 136 + kk], 136);
                wmma::load_matrix_sync(b0, &Was[kk * 136 + gwarp * 32], 136);
                wmma::load_matrix_sync(b1, &Was[kk * 136 + gwarp * 32 + 16], 136);
                wmma::mma_sync(acc[0][0], a0, b0, acc[0][0]);
                wmma::mma_sync(acc[0][1], a0, b1, acc[0][1]);
                wmma::mma_sync(acc[1][0], a1, b0, acc[1][0]);
                wmma::mma_sync(acc[1][1], a1, b1, acc[1][1]);
            }
#pragma unroll
            for (int i = 0; i < 2; i++)
#pragma unroll
                for (int j = 0; j < 2; j++)
                    wmma::store_matrix_sync(&Sf[(i * 16) * 132 + gwarp * 32 + j * 16],
                                            acc[i][j], 132, wmma::mem_row_major);
        }
        BARG();

        // phase 5: s = ReLU(wg * Sf + ba) . Wb -> g_s (no trailing barrier)
#pragma unroll
        for (int t = 0; t < 8; t++) {
            int e = gwarp * 8 + t;
            float wg = wgv[e];
            float p = 0.f;
#pragma unroll
            for (int u = 0; u < 4; u++) {
                int c = lane + 32 * u;
                p = fmaf(fmaxf(fmaf(wg, Sf[e * 132 + c], p_ba[c]), 0.f), p_Wb[c], p);
            }
#pragma unroll
            for (int o = 16; o; o >>= 1) p += __shfl_xor_sync(0xffffffffu, p, o);
            if (lane == 0) g_s[e0 + e] = p;
        }
    }
}

// ================= aggregation (slot order, 2-edge ILP; fused head; resets stats) =====
__global__ void __launch_bounds__(256)
k_agg(const float* __restrict__ xin, float* __restrict__ xout,
      int is_final,
      const float* __restrict__ We, const float* __restrict__ be,
      float* __restrict__ out) {
    if (blockIdx.x == 0 && threadIdx.x < 2 * NH) g_stats[threadIdx.x] = 0.f;
    int n = blockIdx.x * 8 + (threadIdx.x >> 5);
    if (n >= N_NODES_C) return;
    int lane = threadIdx.x & 31;
    float4 xi = *(const float4*)&xin[(size_t)n * NH + lane * 4];
    float4 acc = xi;
    int beg = g_rowptr[n], end = g_rowptr[n + 1];
    int j = beg;
    for (; j + 1 < end; j += 2) {
        float s0 = g_s[j], s1 = g_s[j + 1];
        int c0 = g_colj[j], c1 = g_colj[j + 1];
        float4 xc0 = *(const float4*)&xin[(size_t)c0 * NH + lane * 4];
        float4 xc1 = *(const float4*)&xin[(size_t)c1 * NH + lane * 4];
        acc.x += fminf(fmaxf((xi.x - xc0.x) * s0, -100.f), 100.f)
               + fminf(fmaxf((xi.x - xc1.x) * s1, -100.f), 100.f);
        acc.y += fminf(fmaxf((xi.y - xc0.y) * s0, -100.f), 100.f)
               + fminf(fmaxf((xi.y - xc1.y) * s1, -100.f), 100.f);
        acc.z += fminf(fmaxf((xi.z - xc0.z) * s0, -100.f), 100.f)
               + fminf(fmaxf((xi.z - xc1.z) * s1, -100.f), 100.f);
        acc.w += fminf(fmaxf((xi.w - xc0.w) * s0, -100.f), 100.f)
               + fminf(fmaxf((xi.w - xc1.w) * s1, -100.f), 100.f);
    }
    if (j < end) {
        float s = g_s[j];
        int c = g_colj[j];
        float4 xc = *(const float4*)&xin[(size_t)c * NH + lane * 4];
        acc.x += fminf(fmaxf((xi.x - xc.x) * s, -100.f), 100.f);
        acc.y += fminf(fmaxf((xi.y - xc.y) * s, -100.f), 100.f);
        acc.z += fminf(fmaxf((xi.z - xc.z) * s, -100.f), 100.f);
        acc.w += fminf(fmaxf((xi.w - xc.w) * s, -100.f), 100.f);
    }
    if (is_final) {
        int k0 = lane * 4;
        float p0 = acc.x * We[k0 * 2] + acc.y * We[(k0 + 1) * 2]
                 + acc.z * We[(k0 + 2) * 2] + acc.w * We[(k0 + 3) * 2];
        float p1 = acc.x * We[k0 * 2 + 1] + acc.y * We[(k0 + 1) * 2 + 1]
                 + acc.z * We[(k0 + 2) * 2 + 1] + acc.w * We[(k0 + 3) * 2 + 1];
#pragma unroll
        for (int o = 16; o; o >>= 1) {
            p0 += __shfl_xor_sync(0xffffffffu, p0, o);
            p1 += __shfl_xor_sync(0xffffffffu, p1, o);
        }
        if (lane == 0) {
            out[(size_t)n * 2 + 0] = sigmoid_f(p0 + be[0]);
            out[(size_t)n * 2 + 1] = sigmoid_f(p1 + be[1]);
        }
    } else {
        *(float4*)&xout[(size_t)n * NH + lane * 4] = acc;
    }
}

// ================= launch ==============================================================
extern "C" void kernel_launch(void* const* d_in, const int* in_sizes, int n_in,
                              void* d_out, int out_size) {
    (void)in_sizes; (void)n_in; (void)out_size;
    const float* x     = (const float*)d_in[0];
    const int*   ei    = (const int*)d_in[1];
    const float* ea    = (const float*)d_in[2];
    const float* W1    = (const float*)d_in[3];
    const float* gamma = (const float*)d_in[4];
    const float* beta  = (const float*)d_in[5];
    const float* W2    = (const float*)d_in[6];
    const float* b2    = (const float*)d_in[7];
    const float* Wa    = (const float*)d_in[8];
    const float* ba    = (const float*)d_in[9];
    const float* Wb    = (const float*)d_in[10];
    const float* Wm    = (const float*)d_in[11];
    const float* bm    = (const float*)d_in[12];
    const float* We    = (const float*)d_in[13];
    const float* be    = (const float*)d_in[14];
    float* out = (float*)d_out;

    const int smem_node  = 128 * 264 * 2 + 64 * 136 * 2;
    const int smem_fused = 2 * 128 * 136 * 2
                         + 4 * 32 * 136 * 2
                         + 4 * 32 * 132 * 4
                         + (6 * 128 + 128) * 4;
    cudaFuncSetAttribute(k_node,  cudaFuncAttributeMaxDynamicSharedMemorySize, smem_node);
    cudaFuncSetAttribute(k_fused, cudaFuncAttributeMaxDynamicSharedMemorySize, smem_fused);

    void *px = nullptr, *pcnt = nullptr, *pstats = nullptr, *px2 = nullptr;
    cudaGetSymbolAddress(&px, g_x);
    cudaGetSymbolAddress(&px2, g_x2);
    cudaGetSymbolAddress(&pcnt, g_cnt);
    cudaGetSymbolAddress(&pstats, g_stats);

    cudaMemcpyAsync(px, x, sizeof(float) * N_NODES_C * NH, cudaMemcpyDeviceToDevice, 0);
    cudaMemsetAsync(pcnt, 0, N_NODES_C * sizeof(int), 0);
    cudaMemsetAsync(pstats, 0, 2 * NH * sizeof(float), 0);

    k_hist<<<(N_EDGES_C + 255) / 256, 256>>>(ei);
    k_scan<<<1, 1024>>>();
    k_fillcsr<<<(N_EDGES_C + 255) / 256, 256>>>(ei);
    k_sortseg<<<(N_NODES_C + 255) / 256, 256>>>();
    k_perm<<<(N_EDGES_C + 255) / 256, 256>>>(ei, ea);

    float* bufA = (float*)px;
    float* bufB = (float*)px2;

    for (int l = 0; l < NLAYERS; l++) {
        const float* W1l = W1 + (size_t)l * DIN * NH;
        const float* xin  = (l & 1) ? bufB : bufA;
        float*       xout = (l & 1) ? bufA : bufB;
        int is_final = (l == NLAYERS - 1);
        k_node<<<GRID_P * 2, 256, smem_node>>>(xin, W1l);
        k_stats<<<1184, 256>>>(xin, W1l + 256 * NH);
        k_fused<<<GRID_P, 512, smem_fused>>>(gamma + l * NH, beta + l * NH,
                                             W2 + (size_t)l * NH * NH, b2 + l * NH,
                                             Wa + (size_t)l * NH * NH, ba + l * NH,
                                             Wb + l * NH,
                                             Wm + l * NH, bm + l);
        k_agg<<<(N_NODES_C + 7) / 8, 256>>>(xin, xout, is_final, We, be, out);
    }
}

// round 15
// speedup vs baseline: 1.0205x; 1.0205x over previous
#include <cuda_runtime.h>
#include <cuda_bf16.h>
#include <mma.h>
#include <math.h>

using namespace nvcuda;

#define N_NODES_C 20000
#define N_EDGES_C 320000
#define NH 128
#define DIN 262
#define NLAYERS 3
#define BN_EPS 1e-5f
#define GRID_P 148

typedef unsigned long long ull;

// ---------------- scratch ----------------
__device__ float g_x[N_NODES_C * NH];
__device__ float g_x2[N_NODES_C * NH];
__device__ float g_Y[(size_t)N_NODES_C * 256];              // [Y1 | Y2] per node
__device__ __nv_bfloat16 g_h[(size_t)N_EDGES_C * NH];       // hpre (bf16, slot order)
__device__ float g_s[N_EDGES_C];                            // per-slot phi_x scalar
__device__ float g_eap[N_EDGES_C * 4];                      // permuted edge_attr
__device__ int   g_colj[N_EDGES_C];                         // permuted col index
__device__ float g_stats[2 * NH];
__device__ int   g_cnt[N_NODES_C];
__device__ int   g_rowptr[N_NODES_C + 1];
__device__ int   g_eidx[N_EDGES_C];

__device__ __forceinline__ float psi_f(float z) {
    return copysignf(log1pf(fabsf(z)), z);
}
__device__ __forceinline__ float sigmoid_f(float z) {
    return 1.0f / (1.0f + expf(-z));
}
__device__ __forceinline__ __nv_bfloat16 bf(float x) { return __float2bfloat16(x); }

// ---- packed fp32x2 helpers (sm_103a; ptxas never emits FFMA2 from C++) ----
__device__ __forceinline__ ull pk2(float lo, float hi) {
    ull r; asm("mov.b64 %0, {%1, %2};" : "=l"(r) : "f"(lo), "f"(hi)); return r;
}
__device__ __forceinline__ void upk2(ull v, float& lo, float& hi) {
    asm("mov.b64 {%0, %1}, %2;" : "=f"(lo), "=f"(hi) : "l"(v));
}
__device__ __forceinline__ ull fma2(ull a, ull b, ull c) {
    ull d; asm("fma.rn.f32x2 %0, %1, %2, %3;" : "=l"(d) : "l"(a), "l"(b), "l"(c)); return d;
}
__device__ __forceinline__ ull add2(ull a, ull b) {
    ull d; asm("add.rn.f32x2 %0, %1, %2;" : "=l"(d) : "l"(a), "l"(b)); return d;
}

typedef wmma::fragment<wmma::matrix_a, 16, 16, 16, __nv_bfloat16, wmma::row_major> FragA;
typedef wmma::fragment<wmma::matrix_b, 16, 16, 16, __nv_bfloat16, wmma::row_major> FragB;
typedef wmma::fragment<wmma::accumulator, 16, 16, 16, float> FragC;

// ================= CSR build (once per launch) ========================================
__global__ void k_hist(const int* __restrict__ ei) {
    int e = blockIdx.x * 256 + threadIdx.x;
    if (e < N_EDGES_C) atomicAdd(&g_cnt[ei[e]], 1);
}

__global__ void k_scan() {
    __shared__ int part[1024];
    int t = threadIdx.x;
    int base = t * 20;
    int s = 0;
    for (int i = 0; i < 20; i++) {
        int idx = base + i;
        if (idx < N_NODES_C) s += g_cnt[idx];
    }
    part[t] = s;
    __syncthreads();
    for (int off = 1; off < 1024; off <<= 1) {
        int v = (t >= off) ? part[t - off] : 0;
        __syncthreads();
        part[t] += v;
        __syncthreads();
    }
    int run = (t == 0) ? 0 : part[t - 1];
    for (int i = 0; i < 20; i++) {
        int idx = base + i;
        if (idx <= N_NODES_C) g_rowptr[idx] = run;
        if (idx < N_NODES_C) run += g_cnt[idx];
    }
    for (int i = 0; i < 20; i++) {
        int idx = base + i;
        if (idx < N_NODES_C) g_cnt[idx] = 0;
    }
}

__global__ void k_fillcsr(const int* __restrict__ ei) {
    int e = blockIdx.x * 256 + threadIdx.x;
    if (e < N_EDGES_C) {
        int r = ei[e];
        int slot = g_rowptr[r] + atomicAdd(&g_cnt[r], 1);
        g_eidx[slot] = e;
    }
}

// warp-per-node rank sort (edge ids are distinct -> rank is a permutation)
__global__ void k_sortseg() {
    int n = blockIdx.x * 8 + (threadIdx.x >> 5);
    if (n >= N_NODES_C) return;
    int lane = threadIdx.x & 31;
    int beg = g_rowptr[n], end = g_rowptr[n + 1];
    int d = end - beg;
    if (d <= 1) return;
    if (d <= 128) {
        int vals[4], ranks[4];
        int cnt = 0;
        for (int i = beg + lane; i < end; i += 32) vals[cnt++] = g_eidx[i];
        for (int t = 0; t < cnt; t++) {
            int v = vals[t], r = 0;
            for (int j = beg; j < end; j++) r += (g_eidx[j] < v);
            ranks[t] = r;
        }
        __syncwarp();
        for (int t = 0; t < cnt; t++) g_eidx[beg + ranks[t]] = vals[t];
    } else if (lane == 0) {
        for (int i = beg + 1; i < end; i++) {
            int v = g_eidx[i], j = i - 1;
            while (j >= beg && g_eidx[j] > v) { g_eidx[j + 1] = g_eidx[j]; j--; }
            g_eidx[j + 1] = v;
        }
    }
}

__global__ void k_perm(const int* __restrict__ ei, const float* __restrict__ ea) {
    int j = blockIdx.x * 256 + threadIdx.x;
    if (j < N_EDGES_C) {
        int e = g_eidx[j];
        g_colj[j] = ei[N_EDGES_C + e];
        *(float4*)&g_eap[(size_t)j * 4] = *(const float4*)&ea[(size_t)e * 4];
    }
}

// ================= node GEMM: Y = X @ [W1a | W1b] (2 CTAs/SM) =========================
__global__ void __launch_bounds__(256, 2)
k_node(const float* __restrict__ xin, const float* __restrict__ W1) {
    extern __shared__ __align__(16) char smraw[];
    __nv_bfloat16* Bs = (__nv_bfloat16*)smraw;        // 128 x 264
    __nv_bfloat16* As = Bs + 128 * 264;               // 64 x 136

    int tid = threadIdx.x;
    int warp = tid >> 5;
    int wy = warp >> 2, wx = warp & 3;

    for (int idx = tid; idx < 128 * 256; idx += 256) {
        int k = idx >> 8, c = idx & 255;
        float v = (c < 128) ? W1[(size_t)k * NH + c] : W1[(size_t)(128 + k) * NH + (c - 128)];
        Bs[k * 264 + c] = bf(v);
    }

    const int NT = (N_NODES_C + 63) / 64;   // 313
    for (int tile = blockIdx.x; tile < NT; tile += GRID_P * 2) {
        int n0 = tile * 64;
        __syncthreads();
        for (int idx = tid; idx < 64 * 32; idx += 256) {
            int e = idx >> 5, g = idx & 31;
            int r = n0 + e; if (r >= N_NODES_C) r = N_NODES_C - 1;
            float4 v = *(const float4*)&xin[(size_t)r * NH + g * 4];
            __nv_bfloat16* dst = &As[e * 136 + g * 4];
            dst[0] = bf(v.x); dst[1] = bf(v.y); dst[2] = bf(v.z); dst[3] = bf(v.w);
        }
        __syncthreads();

        FragC acc[2][4];
#pragma unroll
        for (int i = 0; i < 2; i++)
#pragma unroll
            for (int j = 0; j < 4; j++) wmma::fill_fragment(acc[i][j], 0.f);

#pragma unroll
        for (int kk = 0; kk < NH; kk += 16) {
            FragA a0, a1;
            wmma::load_matrix_sync(a0, &As[(wy * 32) * 136 + kk], 136);
            wmma::load_matrix_sync(a1, &As[(wy * 32 + 16) * 136 + kk], 136);
#pragma unroll
            for (int j = 0; j < 4; j++) {
                FragB bfr;
                wmma::load_matrix_sync(bfr, &Bs[kk * 264 + wx * 64 + j * 16], 264);
                wmma::mma_sync(acc[0][j], a0, bfr, acc[0][j]);
                wmma::mma_sync(acc[1][j], a1, bfr, acc[1][j]);
            }
        }
#pragma unroll
        for (int i = 0; i < 2; i++) {
            int row0 = n0 + wy * 32 + i * 16;
            if (row0 + 16 <= N_NODES_C) {
#pragma unroll
                for (int j = 0; j < 4; j++)
                    wmma::store_matrix_sync(&g_Y[(size_t)row0 * 256 + wx * 64 + j * 16],
                                            acc[i][j], 256, wmma::mem_row_major);
            }
        }
    }
}

// ================= stats pass: warp-per-node, 2-edge ILP, packed f32x2 chain ==========
__global__ void __launch_bounds__(256)
k_stats(const float* __restrict__ xin, const float* __restrict__ W1c) {
    __shared__ __align__(16) float w1c[6 * 128];
    __shared__ float red[2 * 128];

    int tid = threadIdx.x;
    int warp = tid >> 5, lane = tid & 31;
    for (int i = tid; i < 6 * 128; i += 256) w1c[i] = W1c[i];
    if (tid < 256) red[tid] = 0.f;
    __syncthreads();

    int col = lane * 4;
    float sgn0 = (lane == 0) ? 1.f : -1.f;

    // packed accumulators: [pair0 = cols col..col+1, pair1 = cols col+2..col+3]
    ull as0 = 0, as1 = 0, aq0 = 0, aq1 = 0;   // 0x0 == packed {0.f, 0.f}

    // weight row pairs (resident per thread, 64-bit smem loads)
    const ull* w64 = (const ull*)w1c;

    int gw = blockIdx.x * 8 + warp;
    int tw = gridDim.x * 8;
    for (int n = gw; n < N_NODES_C; n += tw) {
        float4 xr = *(const float4*)&xin[(size_t)n * NH + col];
        float4 y1 = *(const float4*)&g_Y[(size_t)n * 256 + col];
        ull hbp0 = pk2(y1.x, y1.y);
        ull hbp1 = pk2(y1.z, y1.w);
        int beg = g_rowptr[n], end = g_rowptr[n + 1];
        int j = beg;

        for (; j + 1 < end; j += 2) {
            int c0 = g_colj[j];
            int c1 = g_colj[j + 1];
            float4 xc0 = *(const float4*)&xin[(size_t)c0 * NH + col];
            float4 xc1 = *(const float4*)&xin[(size_t)c1 * NH + col];
            float4 y20 = *(const float4*)&g_Y[(size_t)c0 * 256 + 128 + col];
            float4 y21 = *(const float4*)&g_Y[(size_t)c1 * 256 + 128 + col];
            float4 ev0 = *(const float4*)&g_eap[(size_t)j * 4];
            float4 ev1 = *(const float4*)&g_eap[(size_t)(j + 1) * 4];

            float d0x = xr.x - xc0.x, d0y = xr.y - xc0.y, d0z = xr.z - xc0.z, d0w = xr.w - xc0.w;
            float d1x = xr.x - xc1.x, d1y = xr.y - xc1.y, d1z = xr.z - xc1.z, d1w = xr.w - xc1.w;
            float dd0 = sgn0 * d0x * d0x - d0y * d0y - d0z * d0z - d0w * d0w;
            float ij0 = sgn0 * xr.x * xc0.x - xr.y * xc0.y - xr.z * xc0.z - xr.w * xc0.w;
            float dd1 = sgn0 * d1x * d1x - d1y * d1y - d1z * d1z - d1w * d1w;
            float ij1 = sgn0 * xr.x * xc1.x - xr.y * xc1.y - xr.z * xc1.z - xr.w * xc1.w;
#pragma unroll
            for (int o = 16; o; o >>= 1) {
                dd0 += __shfl_xor_sync(0xffffffffu, dd0, o);
                ij0 += __shfl_xor_sync(0xffffffffu, ij0, o);
                dd1 += __shfl_xor_sync(0xffffffffu, dd1, o);
                ij1 += __shfl_xor_sync(0xffffffffu, ij1, o);
            }
            float nrm0 = psi_f(dd0), dt0 = psi_f(ij0);
            float nrm1 = psi_f(dd1), dt1 = psi_f(ij1);

            // weight pairs (shared by both edges)
            ull w0a = w64[(0 * 128 + col) >> 1], w0b = w64[(0 * 128 + col + 2) >> 1];
            ull w1a = w64[(1 * 128 + col) >> 1], w1b = w64[(1 * 128 + col + 2) >> 1];
            ull w2a = w64[(2 * 128 + col) >> 1], w2b = w64[(2 * 128 + col + 2) >> 1];
            ull w3a = w64[(3 * 128 + col) >> 1], w3b = w64[(3 * 128 + col + 2) >> 1];
            ull w4a = w64[(4 * 128 + col) >> 1], w4b = w64[(4 * 128 + col + 2) >> 1];
            ull w5a = w64[(5 * 128 + col) >> 1], w5b = w64[(5 * 128 + col + 2) >> 1];

            // edge 0
            {
                ull ex = pk2(ev0.x, ev0.x), ey = pk2(ev0.y, ev0.y);
                ull ez = pk2(ev0.z, ev0.z), ew = pk2(ev0.w, ev0.w);
                ull en = pk2(nrm0, nrm0),   et = pk2(dt0, dt0);
                ull h0 = add2(hbp0, pk2(y20.x, y20.y));
                ull h1 = add2(hbp1, pk2(y20.z, y20.w));
                h0 = fma2(ex, w0a, h0);  h1 = fma2(ex, w0b, h1);
                h0 = fma2(ey, w1a, h0);  h1 = fma2(ey, w1b, h1);
                h0 = fma2(ez, w2a, h0);  h1 = fma2(ez, w2b, h1);
                h0 = fma2(ew, w3a, h0);  h1 = fma2(ew, w3b, h1);
                h0 = fma2(en, w4a, h0);  h1 = fma2(en, w4b, h1);
                h0 = fma2(et, w5a, h0);  h1 = fma2(et, w5b, h1);
                as0 = add2(as0, h0);  as1 = add2(as1, h1);
                aq0 = fma2(h0, h0, aq0);  aq1 = fma2(h1, h1, aq1);
                float f0, f1, f2, f3;
                upk2(h0, f0, f1); upk2(h1, f2, f3);
                __nv_bfloat162 a = __floats2bfloat162_rn(f0, f1);
                __nv_bfloat162 b = __floats2bfloat162_rn(f2, f3);
                uint2 pk; pk.x = *(unsigned int*)&a; pk.y = *(unsigned int*)&b;
                *(uint2*)&g_h[(size_t)j * NH + col] = pk;
            }
            // edge 1
            {
                ull ex = pk2(ev1.x, ev1.x), ey = pk2(ev1.y, ev1.y);
                ull ez = pk2(ev1.z, ev1.z), ew = pk2(ev1.w, ev1.w);
                ull en = pk2(nrm1, nrm1),   et = pk2(dt1, dt1);
                ull h0 = add2(hbp0, pk2(y21.x, y21.y));
                ull h1 = add2(hbp1, pk2(y21.z, y21.w));
                h0 = fma2(ex, w0a, h0);  h1 = fma2(ex, w0b, h1);
                h0 = fma2(ey, w1a, h0);  h1 = fma2(ey, w1b, h1);
                h0 = fma2(ez, w2a, h0);  h1 = fma2(ez, w2b, h1);
                h0 = fma2(ew, w3a, h0);  h1 = fma2(ew, w3b, h1);
                h0 = fma2(en, w4a, h0);  h1 = fma2(en, w4b, h1);
                h0 = fma2(et, w5a, h0);  h1 = fma2(et, w5b, h1);
                as0 = add2(as0, h0);  as1 = add2(as1, h1);
                aq0 = fma2(h0, h0, aq0);  aq1 = fma2(h1, h1, aq1);
                float f0, f1, f2, f3;
                upk2(h0, f0, f1); upk2(h1, f2, f3);
                __nv_bfloat162 a = __floats2bfloat162_rn(f0, f1);
                __nv_bfloat162 b = __floats2bfloat162_rn(f2, f3);
                uint2 pk; pk.x = *(unsigned int*)&a; pk.y = *(unsigned int*)&b;
                *(uint2*)&g_h[(size_t)(j + 1) * NH + col] = pk;
            }
        }

        // tail edge
        if (j < end) {
            int c = g_colj[j];
            float4 xc = *(const float4*)&xin[(size_t)c * NH + col];
            float4 y2 = *(const float4*)&g_Y[(size_t)c * 256 + 128 + col];
            float dx = xr.x - xc.x, dy = xr.y - xc.y, dz = xr.z - xc.z, dw = xr.w - xc.w;
            float dd = sgn0 * dx * dx - dy * dy - dz * dz - dw * dw;
            float ij = sgn0 * xr.x * xc.x - xr.y * xc.y - xr.z * xc.z - xr.w * xc.w;
#pragma unroll
            for (int o = 16; o; o >>= 1) {
                dd += __shfl_xor_sync(0xffffffffu, dd, o);
                ij += __shfl_xor_sync(0xffffffffu, ij, o);
            }
            float nrm = psi_f(dd), dt = psi_f(ij);
            float4 eav = *(const float4*)&g_eap[(size_t)j * 4];
            ull ex = pk2(eav.x, eav.x), ey = pk2(eav.y, eav.y);
            ull ez = pk2(eav.z, eav.z), ew = pk2(eav.w, eav.w);
            ull en = pk2(nrm, nrm),     et = pk2(dt, dt);
            ull h0 = add2(hbp0, pk2(y2.x, y2.y));
            ull h1 = add2(hbp1, pk2(y2.z, y2.w));
            h0 = fma2(ex, w64[(0 * 128 + col) >> 1], h0);  h1 = fma2(ex, w64[(0 * 128 + col + 2) >> 1], h1);
            h0 = fma2(ey, w64[(1 * 128 + col) >> 1], h0);  h1 = fma2(ey, w64[(1 * 128 + col + 2) >> 1], h1);
            h0 = fma2(ez, w64[(2 * 128 + col) >> 1], h0);  h1 = fma2(ez, w64[(2 * 128 + col + 2) >> 1], h1);
            h0 = fma2(ew, w64[(3 * 128 + col) >> 1], h0);  h1 = fma2(ew, w64[(3 * 128 + col + 2) >> 1], h1);
            h0 = fma2(en, w64[(4 * 128 + col) >> 1], h0);  h1 = fma2(en, w64[(4 * 128 + col + 2) >> 1], h1);
            h0 = fma2(et, w64[(5 * 128 + col) >> 1], h0);  h1 = fma2(et, w64[(5 * 128 + col + 2) >> 1], h1);
            as0 = add2(as0, h0);  as1 = add2(as1, h1);
            aq0 = fma2(h0, h0, aq0);  aq1 = fma2(h1, h1, aq1);
            float f0, f1, f2, f3;
            upk2(h0, f0, f1); upk2(h1, f2, f3);
            __nv_bfloat162 a = __floats2bfloat162_rn(f0, f1);
            __nv_bfloat162 b = __floats2bfloat162_rn(f2, f3);
            uint2 pk; pk.x = *(unsigned int*)&a; pk.y = *(unsigned int*)&b;
            *(uint2*)&g_h[(size_t)j * NH + col] = pk;
        }
    }

    // unpack accumulators and reduce
    {
        float s0, s1, s2, s3, q0, q1, q2, q3;
        upk2(as0, s0, s1); upk2(as1, s2, s3);
        upk2(aq0, q0, q1); upk2(aq1, q2, q3);
        atomicAdd(&red[col + 0], s0); atomicAdd(&red[col + 1], s1);
        atomicAdd(&red[col + 2], s2); atomicAdd(&red[col + 3], s3);
        atomicAdd(&red[128 + col + 0], q0); atomicAdd(&red[128 + col + 1], q1);
        atomicAdd(&red[128 + col + 2], q2); atomicAdd(&red[128 + col + 3], q3);
    }
    __syncthreads();
    if (tid < 256) atomicAdd(&g_stats[tid], red[tid]);
}

// ================= fused edge MLP: FOUR 4-warp pipelines, in-CTA BN finalize ==========
#define BARG() asm volatile("bar.sync %0, 128;" :: "r"(group + 1) : "memory")

__global__ void __launch_bounds__(512, 1)
k_fused(const float* __restrict__ gamma, const float* __restrict__ beta,
        const float* __restrict__ W2, const float* __restrict__ b2,
        const float* __restrict__ Wa, const float* __restrict__ ba,
        const float* __restrict__ Wb,
        const float* __restrict__ Wm, const float* __restrict__ bm) {
    extern __shared__ __align__(16) char smraw[];
    __nv_bfloat16* W2s = (__nv_bfloat16*)smraw;       // 128 x 136
    __nv_bfloat16* Was = W2s + 128 * 136;             // 128 x 136
    __nv_bfloat16* Sall = Was + 128 * 136;            // 4 x (32 x 136) bf16
    float* Sfall = (float*)(Sall + 4 * 32 * 136);     // 4 x (32 x 132) fp32
    float* p_bnA = Sfall + 4 * 32 * 132;
    float* p_bnB = p_bnA + NH;
    float* p_b2  = p_bnB + NH;
    float* p_ba  = p_b2 + NH;
    float* p_Wm  = p_ba + NH;
    float* p_Wb  = p_Wm + NH;
    float* wg_all = p_Wb + NH;                        // 4 x 32

    int tid = threadIdx.x;
    int warp = tid >> 5, lane = tid & 31;
    int group = warp >> 2;                 // 0..3
    int gwarp = warp & 3;                  // 0..3 (column quarter)
    float bmv = bm[0];

    __nv_bfloat16* S  = Sall + group * 32 * 136;
    float*         Sf = Sfall + group * 32 * 132;
    float*         wgv = wg_all + group * 32;

    for (int idx = tid; idx < NH * NH; idx += 512) {
        int k = idx >> 7, c = idx & 127;
        W2s[k * 136 + c] = bf(W2[idx]);
        Was[k * 136 + c] = bf(Wa[idx]);
    }
    if (tid < NH) {
        float inv = 1.f / (float)N_EDGES_C;
        float mean = g_stats[tid] * inv;
        float var = g_stats[NH + tid] * inv - mean * mean;
        float sc = gamma[tid] * rsqrtf(var + BN_EPS);
        p_bnA[tid] = sc;
        p_bnB[tid] = beta[tid] - mean * sc;
        p_b2[tid]  = b2[tid];
        p_ba[tid]  = ba[tid];
        p_Wm[tid]  = Wm[tid];
        p_Wb[tid]  = Wb[tid];
    }
    __syncthreads();

    const int NT = N_EDGES_C / 32;          // 10000
    int tid_g = tid & 127;
    int pe = tid_g >> 4, pg = tid_g & 15;

    int tile = blockIdx.x * 4 + group;
    uint4 pre[4];
    if (tile < NT) {
#pragma unroll
        for (int it = 0; it < 4; it++) {
            int e = pe + it * 8;
            pre[it] = *(const uint4*)&g_h[(size_t)(tile * 32 + e) * NH + pg * 8];
        }
    }

    for (; tile < NT; tile += GRID_P * 4) {
        int e0 = tile * 32;

        // phase 1: convert prefetched hpre; BN + ReLU -> S
#pragma unroll
        for (int it = 0; it < 4; it++) {
            int e = pe + it * 8;
            __nv_bfloat162* hp = (__nv_bfloat162*)&pre[it];
            int cc0 = pg * 8;
            uint4 outp;
            __nv_bfloat162* op = (__nv_bfloat162*)&outp;
#pragma unroll
            for (int q = 0; q < 4; q++) {
                float2 f = __bfloat1622float2(hp[q]);
                int c0 = cc0 + q * 2;
                float v0 = fmaxf(fmaf(f.x, p_bnA[c0 + 0], p_bnB[c0 + 0]), 0.f);
                float v1 = fmaxf(fmaf(f.y, p_bnA[c0 + 1], p_bnB[c0 + 1]), 0.f);
                op[q] = __floats2bfloat162_rn(v0, v1);
            }
            *(uint4*)&S[e * 136 + pg * 8] = outp;
        }
        {
            int ntile = tile + GRID_P * 4;
            if (ntile < NT) {
#pragma unroll
                for (int it = 0; it < 4; it++) {
                    int e = pe + it * 8;
                    pre[it] = *(const uint4*)&g_h[(size_t)(ntile * 32 + e) * NH + pg * 8];
                }
            }
        }
        BARG();

        // phase 2: Sf = S @ W2
        {
            FragC acc[2][2];
#pragma unroll
            for (int i = 0; i < 2; i++)
#pragma unroll
                for (int j = 0; j < 2; j++) wmma::fill_fragment(acc[i][j], 0.f);
#pragma unroll
            for (int kk = 0; kk < NH; kk += 16) {
                FragA a0, a1; FragB b0, b1;
                wmma::load_matrix_sync(a0, &S[0 * 136 + kk], 136);
                wmma::load_matrix_sync(a1, &S[16 * 136 + kk], 136);
                wmma::load_matrix_sync(b0, &W2s[kk * 136 + gwarp * 32], 136);
                wmma::load_matrix_sync(b1, &W2s[kk * 136 + gwarp * 32 + 16], 136);
                wmma::mma_sync(acc[0][0], a0, b0, acc[0][0]);
                wmma::mma_sync(acc[0][1], a0, b1, acc[0][1]);
                wmma::mma_sync(acc[1][0], a1, b0, acc[1][0]);
                wmma::mma_sync(acc[1][1], a1, b1, acc[1][1]);
            }
#pragma unroll
            for (int i = 0; i < 2; i++)
#pragma unroll
                for (int j = 0; j < 2; j++)
                    wmma::store_matrix_sync(&Sf[(i * 16) * 132 + gwarp * 32 + j * 16],
                                            acc[i][j], 132, wmma::mem_row_major);
        }
        BARG();

        // phase 3: bias + ReLU -> S; gate -> wgv
#pragma unroll
        for (int t = 0; t < 8; t++) {
            int e = gwarp * 8 + t;
            float v[4];
            float p = 0.f;
#pragma unroll
            for (int u = 0; u < 4; u++) {
                int c = lane + 32 * u;
                v[u] = fmaxf(Sf[e * 132 + c] + p_b2[c], 0.f);
                p = fmaf(v[u], p_Wm[c], p);
            }
#pragma unroll
            for (int o = 16; o; o >>= 1) p += __shfl_xor_sync(0xffffffffu, p, o);
            if (lane == 0) wgv[e] = sigmoid_f(p + bmv);
#pragma unroll
            for (int u = 0; u < 4; u++) {
                int c = lane + 32 * u;
                S[e * 136 + c] = bf(v[u]);
            }
        }
        BARG();

        // phase 4: Sf = S @ Wa
        {
            FragC acc[2][2];
#pragma unroll
            for (int i = 0; i < 2; i++)
#pragma unroll
                for (int j = 0; j < 2; j++) wmma::fill_fragment(acc[i][j], 0.f);
#pragma unroll
            for (int kk = 0; kk < NH; kk += 16) {
                FragA a0, a1; FragB b0, b1;
                wmma::load_matrix_sync(a0, &S[0 * 136 + kk], 136);
                wmma::load_matrix_sync(a1, &S[16 * 136 + kk], 136);
                wmma::load_matrix_sync(b0, &Was[kk * 136 + gwarp * 32], 136);
                wmma::load_matrix_sync(b1, &Was[kk * 136 + gwarp * 32 + 16], 136);
                wmma::mma_sync(acc[0][0], a0, b0, acc[0][0]);
                wmma::mma_sync(acc[0][1], a0, b1, acc[0][1]);
                wmma::mma_sync(acc[1][0], a1, b0, acc[1][0]);
                wmma::mma_sync(acc[1][1], a1, b1, acc[1][1]);
            }
#pragma unroll
            for (int i = 0; i < 2; i++)
#pragma unroll
                for (int j = 0; j < 2; j++)
                    wmma::store_matrix_sync(&Sf[(i * 16) * 132 + gwarp * 32 + j * 16],
                                            acc[i][j], 132, wmma::mem_row_major);
        }
        BARG();

        // phase 5: s = ReLU(wg * Sf + ba) . Wb -> g_s (no trailing barrier)
#pragma unroll
        for (int t = 0; t < 8; t++) {
            int e = gwarp * 8 + t;
            float wg = wgv[e];
            float p = 0.f;
#pragma unroll
            for (int u = 0; u < 4; u++) {
                int c = lane + 32 * u;
                p = fmaf(fmaxf(fmaf(wg, Sf[e * 132 + c], p_ba[c]), 0.f), p_Wb[c], p);
            }
#pragma unroll
            for (int o = 16; o; o >>= 1) p += __shfl_xor_sync(0xffffffffu, p, o);
            if (lane == 0) g_s[e0 + e] = p;
        }
    }
}

// ================= aggregation (slot order, 4-edge ILP; fused head; resets stats) =====
__global__ void __launch_bounds__(256)
k_agg(const float* __restrict__ xin, float* __restrict__ xout,
      int is_final,
      const float* __restrict__ We, const float* __restrict__ be,
      float* __restrict__ out) {
    if (blockIdx.x == 0 && threadIdx.x < 2 * NH) g_stats[threadIdx.x] = 0.f;
    int n = blockIdx.x * 8 + (threadIdx.x >> 5);
    if (n >= N_NODES_C) return;
    int lane = threadIdx.x & 31;
    float4 xi = *(const float4*)&xin[(size_t)n * NH + lane * 4];
    float4 acc = xi;
    int beg = g_rowptr[n], end = g_rowptr[n + 1];
    int j = beg;
    for (; j + 3 < end; j += 4) {
        float s0 = g_s[j], s1 = g_s[j + 1], s2 = g_s[j + 2], s3 = g_s[j + 3];
        int c0 = g_colj[j], c1 = g_colj[j + 1], c2 = g_colj[j + 2], c3 = g_colj[j + 3];
        float4 x0 = *(const float4*)&xin[(size_t)c0 * NH + lane * 4];
        float4 x1 = *(const float4*)&xin[(size_t)c1 * NH + lane * 4];
        float4 x2 = *(const float4*)&xin[(size_t)c2 * NH + lane * 4];
        float4 x3 = *(const float4*)&xin[(size_t)c3 * NH + lane * 4];
        acc.x += fminf(fmaxf((xi.x - x0.x) * s0, -100.f), 100.f)
               + fminf(fmaxf((xi.x - x1.x) * s1, -100.f), 100.f)
               + fminf(fmaxf((xi.x - x2.x) * s2, -100.f), 100.f)
               + fminf(fmaxf((xi.x - x3.x) * s3, -100.f), 100.f);
        acc.y += fminf(fmaxf((xi.y - x0.y) * s0, -100.f), 100.f)
               + fminf(fmaxf((xi.y - x1.y) * s1, -100.f), 100.f)
               + fminf(fmaxf((xi.y - x2.y) * s2, -100.f), 100.f)
               + fminf(fmaxf((xi.y - x3.y) * s3, -100.f), 100.f);
        acc.z += fminf(fmaxf((xi.z - x0.z) * s0, -100.f), 100.f)
               + fminf(fmaxf((xi.z - x1.z) * s1, -100.f), 100.f)
               + fminf(fmaxf((xi.z - x2.z) * s2, -100.f), 100.f)
               + fminf(fmaxf((xi.z - x3.z) * s3, -100.f), 100.f);
        acc.w += fminf(fmaxf((xi.w - x0.w) * s0, -100.f), 100.f)
               + fminf(fmaxf((xi.w - x1.w) * s1, -100.f), 100.f)
               + fminf(fmaxf((xi.w - x2.w) * s2, -100.f), 100.f)
               + fminf(fmaxf((xi.w - x3.w) * s3, -100.f), 100.f);
    }
    for (; j < end; j++) {
        float s = g_s[j];
        int c = g_colj[j];
        float4 xc = *(const float4*)&xin[(size_t)c * NH + lane * 4];
        acc.x += fminf(fmaxf((xi.x - xc.x) * s, -100.f), 100.f);
        acc.y += fminf(fmaxf((xi.y - xc.y) * s, -100.f), 100.f);
        acc.z += fminf(fmaxf((xi.z - xc.z) * s, -100.f), 100.f);
        acc.w += fminf(fmaxf((xi.w - xc.w) * s, -100.f), 100.f);
    }
    if (is_final) {
        int k0 = lane * 4;
        float p0 = acc.x * We[k0 * 2] + acc.y * We[(k0 + 1) * 2]
                 + acc.z * We[(k0 + 2) * 2] + acc.w * We[(k0 + 3) * 2];
        float p1 = acc.x * We[k0 * 2 + 1] + acc.y * We[(k0 + 1) * 2 + 1]
                 + acc.z * We[(k0 + 2) * 2 + 1] + acc.w * We[(k0 + 3) * 2 + 1];
#pragma unroll
        for (int o = 16; o; o >>= 1) {
            p0 += __shfl_xor_sync(0xffffffffu, p0, o);
            p1 += __shfl_xor_sync(0xffffffffu, p1, o);
        }
        if (lane == 0) {
            out[(size_t)n * 2 + 0] = sigmoid_f(p0 + be[0]);
            out[(size_t)n * 2 + 1] = sigmoid_f(p1 + be[1]);
        }
    } else {
        *(float4*)&xout[(size_t)n * NH + lane * 4] = acc;
    }
}

// ================= launch ==============================================================
extern "C" void kernel_launch(void* const* d_in, const int* in_sizes, int n_in,
                              void* d_out, int out_size) {
    (void)in_sizes; (void)n_in; (void)out_size;
    const float* x     = (const float*)d_in[0];
    const int*   ei    = (const int*)d_in[1];
    const float* ea    = (const float*)d_in[2];
    const float* W1    = (const float*)d_in[3];
    const float* gamma = (const float*)d_in[4];
    const float* beta  = (const float*)d_in[5];
    const float* W2    = (const float*)d_in[6];
    const float* b2    = (const float*)d_in[7];
    const float* Wa    = (const float*)d_in[8];
    const float* ba    = (const float*)d_in[9];
    const float* Wb    = (const float*)d_in[10];
    const float* Wm    = (const float*)d_in[11];
    const float* bm    = (const float*)d_in[12];
    const float* We    = (const float*)d_in[13];
    const float* be    = (const float*)d_in[14];
    float* out = (float*)d_out;

    const int smem_node  = 128 * 264 * 2 + 64 * 136 * 2;
    const int smem_fused = 2 * 128 * 136 * 2
                         + 4 * 32 * 136 * 2
                         + 4 * 32 * 132 * 4
                         + (6 * 128 + 128) * 4;
    cudaFuncSetAttribute(k_node,  cudaFuncAttributeMaxDynamicSharedMemorySize, smem_node);
    cudaFuncSetAttribute(k_fused, cudaFuncAttributeMaxDynamicSharedMemorySize, smem_fused);

    void *px = nullptr, *pcnt = nullptr, *pstats = nullptr, *px2 = nullptr;
    cudaGetSymbolAddress(&px, g_x);
    cudaGetSymbolAddress(&px2, g_x2);
    cudaGetSymbolAddress(&pcnt, g_cnt);
    cudaGetSymbolAddress(&pstats, g_stats);

    cudaMemcpyAsync(px, x, sizeof(float) * N_NODES_C * NH, cudaMemcpyDeviceToDevice, 0);
    cudaMemsetAsync(pcnt, 0, N_NODES_C * sizeof(int), 0);
    cudaMemsetAsync(pstats, 0, 2 * NH * sizeof(float), 0);

    k_hist<<<(N_EDGES_C + 255) / 256, 256>>>(ei);
    k_scan<<<1, 1024>>>();
    k_fillcsr<<<(N_EDGES_C + 255) / 256, 256>>>(ei);
    k_sortseg<<<(N_NODES_C + 7) / 8, 256>>>();
    k_perm<<<(N_EDGES_C + 255) / 256, 256>>>(ei, ea);

    float* bufA = (float*)px;
    float* bufB = (float*)px2;

    for (int l = 0; l < NLAYERS; l++) {
        const float* W1l = W1 + (size_t)l * DIN * NH;
        const float* xin  = (l & 1) ? bufB : bufA;
        float*       xout = (l & 1) ? bufA : bufB;
        int is_final = (l == NLAYERS - 1);
        k_node<<<GRID_P * 2, 256, smem_node>>>(xin, W1l);
        k_stats<<<1184, 256>>>(xin, W1l + 256 * NH);
        k_fused<<<GRID_P, 512, smem_fused>>>(gamma + l * NH, beta + l * NH,
                                             W2 + (size_t)l * NH * NH, b2 + l * NH,
                                             Wa + (size_t)l * NH * NH, ba + l * NH,
                                             Wb + l * NH,
                                             Wm + l * NH, bm + l);
        k_agg<<<(N_NODES_C + 7) / 8, 256>>>(xin, xout, is_final, We, be, out);
    }
}

// round 16
// speedup vs baseline: 1.3607x; 1.3333x over previous
#include <cuda_runtime.h>
#include <cuda_bf16.h>
#include <mma.h>
#include <math.h>

using namespace nvcuda;

#define N_NODES_C 20000
#define N_EDGES_C 320000
#define NH 128
#define DIN 262
#define NLAYERS 3
#define BN_EPS 1e-5f
#define GRID_P 148

typedef unsigned long long ull;
typedef unsigned int uint;

// ---------------- scratch ----------------
__device__ float g_x[N_NODES_C * NH];
__device__ float g_x2[N_NODES_C * NH];
__device__ float g_Y[(size_t)N_NODES_C * 256];              // [Y1 | Y2] per node
__device__ __nv_bfloat16 g_h[(size_t)N_EDGES_C * NH];       // hpre (bf16, slot order)
__device__ float g_s[N_EDGES_C];                            // per-slot phi_x scalar
__device__ float g_eap[N_EDGES_C * 4];                      // permuted edge_attr
__device__ int   g_colj[N_EDGES_C];                         // permuted col index
__device__ float g_stats[2 * NH];
__device__ int   g_cnt[N_NODES_C];
__device__ int   g_rowptr[N_NODES_C + 1];
__device__ int   g_eidx[N_EDGES_C];

__device__ __forceinline__ float psi_f(float z) {
    return copysignf(log1pf(fabsf(z)), z);
}
__device__ __forceinline__ float sigmoid_f(float z) {
    return 1.0f / (1.0f + expf(-z));
}
__device__ __forceinline__ __nv_bfloat16 bf(float x) { return __float2bfloat16(x); }

// ---- packed fp32x2 helpers ----
__device__ __forceinline__ ull pk2(float lo, float hi) {
    ull r; asm("mov.b64 %0, {%1, %2};" : "=l"(r) : "f"(lo), "f"(hi)); return r;
}
__device__ __forceinline__ void upk2(ull v, float& lo, float& hi) {
    asm("mov.b64 {%0, %1}, %2;" : "=f"(lo), "=f"(hi) : "l"(v));
}
__device__ __forceinline__ ull fma2(ull a, ull b, ull c) {
    ull d; asm("fma.rn.f32x2 %0, %1, %2, %3;" : "=l"(d) : "l"(a), "l"(b), "l"(c)); return d;
}
__device__ __forceinline__ ull add2(ull a, ull b) {
    ull d; asm("add.rn.f32x2 %0, %1, %2;" : "=l"(d) : "l"(a), "l"(b)); return d;
}

// ---- raw mma.sync helpers (m16n8k16 bf16, row.col) ----
__device__ __forceinline__ void ldsm_x4(uint& r0, uint& r1, uint& r2, uint& r3, uint addr) {
    asm volatile("ldmatrix.sync.aligned.m8n8.x4.shared.b16 {%0,%1,%2,%3}, [%4];"
                 : "=r"(r0), "=r"(r1), "=r"(r2), "=r"(r3) : "r"(addr));
}
__device__ __forceinline__ void ldsm_x2t(uint& r0, uint& r1, uint addr) {
    asm volatile("ldmatrix.sync.aligned.m8n8.x2.trans.shared.b16 {%0,%1}, [%2];"
                 : "=r"(r0), "=r"(r1) : "r"(addr));
}
__device__ __forceinline__ void mma4(float* d, const uint* a, uint b0, uint b1) {
    asm volatile("mma.sync.aligned.m16n8k16.row.col.f32.bf16.bf16.f32 "
                 "{%0,%1,%2,%3},{%4,%5,%6,%7},{%8,%9},{%0,%1,%2,%3};"
                 : "+f"(d[0]), "+f"(d[1]), "+f"(d[2]), "+f"(d[3])
                 : "r"(a[0]), "r"(a[1]), "r"(a[2]), "r"(a[3]), "r"(b0), "r"(b1));
}

typedef wmma::fragment<wmma::matrix_a, 16, 16, 16, __nv_bfloat16, wmma::row_major> FragA;
typedef wmma::fragment<wmma::matrix_b, 16, 16, 16, __nv_bfloat16, wmma::row_major> FragB;
typedef wmma::fragment<wmma::accumulator, 16, 16, 16, float> FragC;

// ================= CSR build (once per launch) ========================================
__global__ void k_hist(const int* __restrict__ ei) {
    int e = blockIdx.x * 256 + threadIdx.x;
    if (e < N_EDGES_C) atomicAdd(&g_cnt[ei[e]], 1);
}

__global__ void k_scan() {
    __shared__ int part[1024];
    int t = threadIdx.x;
    int base = t * 20;
    int s = 0;
    for (int i = 0; i < 20; i++) {
        int idx = base + i;
        if (idx < N_NODES_C) s += g_cnt[idx];
    }
    part[t] = s;
    __syncthreads();
    for (int off = 1; off < 1024; off <<= 1) {
        int v = (t >= off) ? part[t - off] : 0;
        __syncthreads();
        part[t] += v;
        __syncthreads();
    }
    int run = (t == 0) ? 0 : part[t - 1];
    for (int i = 0; i < 20; i++) {
        int idx = base + i;
        if (idx <= N_NODES_C) g_rowptr[idx] = run;
        if (idx < N_NODES_C) run += g_cnt[idx];
    }
    for (int i = 0; i < 20; i++) {
        int idx = base + i;
        if (idx < N_NODES_C) g_cnt[idx] = 0;
    }
}

__global__ void k_fillcsr(const int* __restrict__ ei) {
    int e = blockIdx.x * 256 + threadIdx.x;
    if (e < N_EDGES_C) {
        int r = ei[e];
        int slot = g_rowptr[r] + atomicAdd(&g_cnt[r], 1);
        g_eidx[slot] = e;
    }
}

__global__ void k_sortseg() {
    int n = blockIdx.x * 8 + (threadIdx.x >> 5);
    if (n >= N_NODES_C) return;
    int lane = threadIdx.x & 31;
    int beg = g_rowptr[n], end = g_rowptr[n + 1];
    int d = end - beg;
    if (d <= 1) return;
    if (d <= 128) {
        int vals[4], ranks[4];
        int cnt = 0;
        for (int i = beg + lane; i < end; i += 32) vals[cnt++] = g_eidx[i];
        for (int t = 0; t < cnt; t++) {
            int v = vals[t], r = 0;
            for (int j = beg; j < end; j++) r += (g_eidx[j] < v);
            ranks[t] = r;
        }
        __syncwarp();
        for (int t = 0; t < cnt; t++) g_eidx[beg + ranks[t]] = vals[t];
    } else if (lane == 0) {
        for (int i = beg + 1; i < end; i++) {
            int v = g_eidx[i], j = i - 1;
            while (j >= beg && g_eidx[j] > v) { g_eidx[j + 1] = g_eidx[j]; j--; }
            g_eidx[j + 1] = v;
        }
    }
}

__global__ void k_perm(const int* __restrict__ ei, const float* __restrict__ ea) {
    int j = blockIdx.x * 256 + threadIdx.x;
    if (j < N_EDGES_C) {
        int e = g_eidx[j];
        g_colj[j] = ei[N_EDGES_C + e];
        *(float4*)&g_eap[(size_t)j * 4] = *(const float4*)&ea[(size_t)e * 4];
    }
}

// ================= node GEMM: Y = X @ [W1a | W1b] (2 CTAs/SM) =========================
__global__ void __launch_bounds__(256, 2)
k_node(const float* __restrict__ xin, const float* __restrict__ W1) {
    extern __shared__ __align__(16) char smraw[];
    __nv_bfloat16* Bs = (__nv_bfloat16*)smraw;        // 128 x 264
    __nv_bfloat16* As = Bs + 128 * 264;               // 64 x 136

    int tid = threadIdx.x;
    int warp = tid >> 5;
    int wy = warp >> 2, wx = warp & 3;

    for (int idx = tid; idx < 128 * 256; idx += 256) {
        int k = idx >> 8, c = idx & 255;
        float v = (c < 128) ? W1[(size_t)k * NH + c] : W1[(size_t)(128 + k) * NH + (c - 128)];
        Bs[k * 264 + c] = bf(v);
    }

    const int NT = (N_NODES_C + 63) / 64;   // 313
    for (int tile = blockIdx.x; tile < NT; tile += GRID_P * 2) {
        int n0 = tile * 64;
        __syncthreads();
        for (int idx = tid; idx < 64 * 32; idx += 256) {
            int e = idx >> 5, g = idx & 31;
            int r = n0 + e; if (r >= N_NODES_C) r = N_NODES_C - 1;
            float4 v = *(const float4*)&xin[(size_t)r * NH + g * 4];
            __nv_bfloat16* dst = &As[e * 136 + g * 4];
            dst[0] = bf(v.x); dst[1] = bf(v.y); dst[2] = bf(v.z); dst[3] = bf(v.w);
        }
        __syncthreads();

        FragC acc[2][4];
#pragma unroll
        for (int i = 0; i < 2; i++)
#pragma unroll
            for (int j = 0; j < 4; j++) wmma::fill_fragment(acc[i][j], 0.f);

#pragma unroll
        for (int kk = 0; kk < NH; kk += 16) {
            FragA a0, a1;
            wmma::load_matrix_sync(a0, &As[(wy * 32) * 136 + kk], 136);
            wmma::load_matrix_sync(a1, &As[(wy * 32 + 16) * 136 + kk], 136);
#pragma unroll
            for (int j = 0; j < 4; j++) {
                FragB bfr;
                wmma::load_matrix_sync(bfr, &Bs[kk * 264 + wx * 64 + j * 16], 264);
                wmma::mma_sync(acc[0][j], a0, bfr, acc[0][j]);
                wmma::mma_sync(acc[1][j], a1, bfr, acc[1][j]);
            }
        }
#pragma unroll
        for (int i = 0; i < 2; i++) {
            int row0 = n0 + wy * 32 + i * 16;
            if (row0 + 16 <= N_NODES_C) {
#pragma unroll
                for (int j = 0; j < 4; j++)
                    wmma::store_matrix_sync(&g_Y[(size_t)row0 * 256 + wx * 64 + j * 16],
                                            acc[i][j], 256, wmma::mem_row_major);
            }
        }
    }
}

// ================= stats pass: warp-per-node, 2-edge ILP, packed f32x2 chain ==========
__global__ void __launch_bounds__(256)
k_stats(const float* __restrict__ xin, const float* __restrict__ W1c) {
    __shared__ __align__(16) float w1c[6 * 128];
    __shared__ float red[2 * 128];

    int tid = threadIdx.x;
    int warp = tid >> 5, lane = tid & 31;
    for (int i = tid; i < 6 * 128; i += 256) w1c[i] = W1c[i];
    if (tid < 256) red[tid] = 0.f;
    __syncthreads();

    int col = lane * 4;
    float sgn0 = (lane == 0) ? 1.f : -1.f;

    ull as0 = 0, as1 = 0, aq0 = 0, aq1 = 0;
    const ull* w64 = (const ull*)w1c;

    int gw = blockIdx.x * 8 + warp;
    int tw = gridDim.x * 8;
    for (int n = gw; n < N_NODES_C; n += tw) {
        float4 xr = *(const float4*)&xin[(size_t)n * NH + col];
        float4 y1 = *(const float4*)&g_Y[(size_t)n * 256 + col];
        ull hbp0 = pk2(y1.x, y1.y);
        ull hbp1 = pk2(y1.z, y1.w);
        int beg = g_rowptr[n], end = g_rowptr[n + 1];
        int j = beg;

        for (; j + 1 < end; j += 2) {
            int c0 = g_colj[j];
            int c1 = g_colj[j + 1];
            float4 xc0 = *(const float4*)&xin[(size_t)c0 * NH + col];
            float4 xc1 = *(const float4*)&xin[(size_t)c1 * NH + col];
            float4 y20 = *(const float4*)&g_Y[(size_t)c0 * 256 + 128 + col];
            float4 y21 = *(const float4*)&g_Y[(size_t)c1 * 256 + 128 + col];
            float4 ev0 = *(const float4*)&g_eap[(size_t)j * 4];
            float4 ev1 = *(const float4*)&g_eap[(size_t)(j + 1) * 4];

            float d0x = xr.x - xc0.x, d0y = xr.y - xc0.y, d0z = xr.z - xc0.z, d0w = xr.w - xc0.w;
            float d1x = xr.x - xc1.x, d1y = xr.y - xc1.y, d1z = xr.z - xc1.z, d1w = xr.w - xc1.w;
            float dd0 = sgn0 * d0x * d0x - d0y * d0y - d0z * d0z - d0w * d0w;
            float ij0 = sgn0 * xr.x * xc0.x - xr.y * xc0.y - xr.z * xc0.z - xr.w * xc0.w;
            float dd1 = sgn0 * d1x * d1x - d1y * d1y - d1z * d1z - d1w * d1w;
            float ij1 = sgn0 * xr.x * xc1.x - xr.y * xc1.y - xr.z * xc1.z - xr.w * xc1.w;
#pragma unroll
            for (int o = 16; o; o >>= 1) {
                dd0 += __shfl_xor_sync(0xffffffffu, dd0, o);
                ij0 += __shfl_xor_sync(0xffffffffu, ij0, o);
                dd1 += __shfl_xor_sync(0xffffffffu, dd1, o);
                ij1 += __shfl_xor_sync(0xffffffffu, ij1, o);
            }
            float nrm0 = psi_f(dd0), dt0 = psi_f(ij0);
            float nrm1 = psi_f(dd1), dt1 = psi_f(ij1);

            ull w0a = w64[(0 * 128 + col) >> 1], w0b = w64[(0 * 128 + col + 2) >> 1];
            ull w1a = w64[(1 * 128 + col) >> 1], w1b = w64[(1 * 128 + col + 2) >> 1];
            ull w2a = w64[(2 * 128 + col) >> 1], w2b = w64[(2 * 128 + col + 2) >> 1];
            ull w3a = w64[(3 * 128 + col) >> 1], w3b = w64[(3 * 128 + col + 2) >> 1];
            ull w4a = w64[(4 * 128 + col) >> 1], w4b = w64[(4 * 128 + col + 2) >> 1];
            ull w5a = w64[(5 * 128 + col) >> 1], w5b = w64[(5 * 128 + col + 2) >> 1];

            {
                ull ex = pk2(ev0.x, ev0.x), ey = pk2(ev0.y, ev0.y);
                ull ez = pk2(ev0.z, ev0.z), ew = pk2(ev0.w, ev0.w);
                ull en = pk2(nrm0, nrm0),   et = pk2(dt0, dt0);
                ull h0 = add2(hbp0, pk2(y20.x, y20.y));
                ull h1 = add2(hbp1, pk2(y20.z, y20.w));
                h0 = fma2(ex, w0a, h0);  h1 = fma2(ex, w0b, h1);
                h0 = fma2(ey, w1a, h0);  h1 = fma2(ey, w1b, h1);
                h0 = fma2(ez, w2a, h0);  h1 = fma2(ez, w2b, h1);
                h0 = fma2(ew, w3a, h0);  h1 = fma2(ew, w3b, h1);
                h0 = fma2(en, w4a, h0);  h1 = fma2(en, w4b, h1);
                h0 = fma2(et, w5a, h0);  h1 = fma2(et, w5b, h1);
                as0 = add2(as0, h0);  as1 = add2(as1, h1);
                aq0 = fma2(h0, h0, aq0);  aq1 = fma2(h1, h1, aq1);
                float f0, f1, f2, f3;
                upk2(h0, f0, f1); upk2(h1, f2, f3);
                __nv_bfloat162 a = __floats2bfloat162_rn(f0, f1);
                __nv_bfloat162 b = __floats2bfloat162_rn(f2, f3);
                uint2 pk; pk.x = *(unsigned int*)&a; pk.y = *(unsigned int*)&b;
                *(uint2*)&g_h[(size_t)j * NH + col] = pk;
            }
            {
                ull ex = pk2(ev1.x, ev1.x), ey = pk2(ev1.y, ev1.y);
                ull ez = pk2(ev1.z, ev1.z), ew = pk2(ev1.w, ev1.w);
                ull en = pk2(nrm1, nrm1),   et = pk2(dt1, dt1);
                ull h0 = add2(hbp0, pk2(y21.x, y21.y));
                ull h1 = add2(hbp1, pk2(y21.z, y21.w));
                h0 = fma2(ex, w0a, h0);  h1 = fma2(ex, w0b, h1);
                h0 = fma2(ey, w1a, h0);  h1 = fma2(ey, w1b, h1);
                h0 = fma2(ez, w2a, h0);  h1 = fma2(ez, w2b, h1);
                h0 = fma2(ew, w3a, h0);  h1 = fma2(ew, w3b, h1);
                h0 = fma2(en, w4a, h0);  h1 = fma2(en, w4b, h1);
                h0 = fma2(et, w5a, h0);  h1 = fma2(et, w5b, h1);
                as0 = add2(as0, h0);  as1 = add2(as1, h1);
                aq0 = fma2(h0, h0, aq0);  aq1 = fma2(h1, h1, aq1);
                float f0, f1, f2, f3;
                upk2(h0, f0, f1); upk2(h1, f2, f3);
                __nv_bfloat162 a = __floats2bfloat162_rn(f0, f1);
                __nv_bfloat162 b = __floats2bfloat162_rn(f2, f3);
                uint2 pk; pk.x = *(unsigned int*)&a; pk.y = *(unsigned int*)&b;
                *(uint2*)&g_h[(size_t)(j + 1) * NH + col] = pk;
            }
        }

        if (j < end) {
            int c = g_colj[j];
            float4 xc = *(const float4*)&xin[(size_t)c * NH + col];
            float4 y2 = *(const float4*)&g_Y[(size_t)c * 256 + 128 + col];
            float dx = xr.x - xc.x, dy = xr.y - xc.y, dz = xr.z - xc.z, dw = xr.w - xc.w;
            float dd = sgn0 * dx * dx - dy * dy - dz * dz - dw * dw;
            float ij = sgn0 * xr.x * xc.x - xr.y * xc.y - xr.z * xc.z - xr.w * xc.w;
#pragma unroll
            for (int o = 16; o; o >>= 1) {
                dd += __shfl_xor_sync(0xffffffffu, dd, o);
                ij += __shfl_xor_sync(0xffffffffu, ij, o);
            }
            float nrm = psi_f(dd), dt = psi_f(ij);
            float4 eav = *(const float4*)&g_eap[(size_t)j * 4];
            ull ex = pk2(eav.x, eav.x), ey = pk2(eav.y, eav.y);
            ull ez = pk2(eav.z, eav.z), ew = pk2(eav.w, eav.w);
            ull en = pk2(nrm, nrm),     et = pk2(dt, dt);
            ull h0 = add2(hbp0, pk2(y2.x, y2.y));
            ull h1 = add2(hbp1, pk2(y2.z, y2.w));
            h0 = fma2(ex, w64[(0 * 128 + col) >> 1], h0);  h1 = fma2(ex, w64[(0 * 128 + col + 2) >> 1], h1);
            h0 = fma2(ey, w64[(1 * 128 + col) >> 1], h0);  h1 = fma2(ey, w64[(1 * 128 + col + 2) >> 1], h1);
            h0 = fma2(ez, w64[(2 * 128 + col) >> 1], h0);  h1 = fma2(ez, w64[(2 * 128 + col + 2) >> 1], h1);
            h0 = fma2(ew, w64[(3 * 128 + col) >> 1], h0);  h1 = fma2(ew, w64[(3 * 128 + col + 2) >> 1], h1);
            h0 = fma2(en, w64[(4 * 128 + col) >> 1], h0);  h1 = fma2(en, w64[(4 * 128 + col + 2) >> 1], h1);
            h0 = fma2(et, w64[(5 * 128 + col) >> 1], h0);  h1 = fma2(et, w64[(5 * 128 + col + 2) >> 1], h1);
            as0 = add2(as0, h0);  as1 = add2(as1, h1);
            aq0 = fma2(h0, h0, aq0);  aq1 = fma2(h1, h1, aq1);
            float f0, f1, f2, f3;
            upk2(h0, f0, f1); upk2(h1, f2, f3);
            __nv_bfloat162 a = __floats2bfloat162_rn(f0, f1);
            __nv_bfloat162 b = __floats2bfloat162_rn(f2, f3);
            uint2 pk; pk.x = *(unsigned int*)&a; pk.y = *(unsigned int*)&b;
            *(uint2*)&g_h[(size_t)j * NH + col] = pk;
        }
    }

    {
        float s0, s1, s2, s3, q0, q1, q2, q3;
        upk2(as0, s0, s1); upk2(as1, s2, s3);
        upk2(aq0, q0, q1); upk2(aq1, q2, q3);
        atomicAdd(&red[col + 0], s0); atomicAdd(&red[col + 1], s1);
        atomicAdd(&red[col + 2], s2); atomicAdd(&red[col + 3], s3);
        atomicAdd(&red[128 + col + 0], q0); atomicAdd(&red[128 + col + 1], q1);
        atomicAdd(&red[128 + col + 2], q2); atomicAdd(&red[128 + col + 3], q3);
    }
    __syncthreads();
    if (tid < 256) atomicAdd(&g_stats[tid], red[tid]);
}

// ================= fused edge MLP v2: raw mma.sync, register epilogues ================
// 512 threads = 4 groups x 4 warps; group tile = 32 edges; warp = 32-column quarter.
// 3 named barriers/tile; no fp32 staging buffer.
#define BARG() asm volatile("bar.sync %0, 128;" :: "r"(group + 1) : "memory")

__global__ void __launch_bounds__(512, 1)
k_fused(const float* __restrict__ gamma, const float* __restrict__ beta,
        const float* __restrict__ W2, const float* __restrict__ b2,
        const float* __restrict__ Wa, const float* __restrict__ ba,
        const float* __restrict__ Wb,
        const float* __restrict__ Wm, const float* __restrict__ bm) {
    extern __shared__ __align__(16) char smraw[];
    __nv_bfloat16* W2s  = (__nv_bfloat16*)smraw;      // 128 x 136
    __nv_bfloat16* Was  = W2s + 128 * 136;            // 128 x 136
    __nv_bfloat16* Sall = Was + 128 * 136;            // 4 x (32 x 136)
    __nv_bfloat16* S2all = Sall + 4 * 32 * 136;       // 4 x (32 x 136)
    float* gp_all = (float*)(S2all + 4 * 32 * 136);   // 4 x 128 (gate partials)
    float* sp_all = gp_all + 4 * 128;                 // 4 x 128 (s partials)
    float* p_bnA = sp_all + 4 * 128;
    float* p_bnB = p_bnA + NH;
    float* p_b2  = p_bnB + NH;
    float* p_ba  = p_b2 + NH;
    float* p_Wm  = p_ba + NH;
    float* p_Wb  = p_Wm + NH;

    int tid = threadIdx.x;
    int warp = tid >> 5, lane = tid & 31;
    int group = warp >> 2;                 // 0..3
    int gwarp = warp & 3;                  // column quarter
    float bmv = bm[0];

    __nv_bfloat16* S  = Sall + group * 32 * 136;
    __nv_bfloat16* S2 = S2all + group * 32 * 136;
    float* gp = gp_all + group * 128;
    float* sp = sp_all + group * 128;

    for (int idx = tid; idx < NH * NH; idx += 512) {
        int k = idx >> 7, c = idx & 127;
        W2s[k * 136 + c] = bf(W2[idx]);
        Was[k * 136 + c] = bf(Wa[idx]);
    }
    if (tid < NH) {
        float inv = 1.f / (float)N_EDGES_C;
        float mean = g_stats[tid] * inv;
        float var = g_stats[NH + tid] * inv - mean * mean;
        float sc = gamma[tid] * rsqrtf(var + BN_EPS);
        p_bnA[tid] = sc;
        p_bnB[tid] = beta[tid] - mean * sc;
        p_b2[tid]  = b2[tid];
        p_ba[tid]  = ba[tid];
        p_Wm[tid]  = Wm[tid];
        p_Wb[tid]  = Wb[tid];
    }
    __syncthreads();

    // shared-space byte addresses for ldmatrix
    uint sS  = (uint)__cvta_generic_to_shared(S);
    uint sS2 = (uint)__cvta_generic_to_shared(S2);
    uint sW2 = (uint)__cvta_generic_to_shared(W2s);
    uint sWa = (uint)__cvta_generic_to_shared(Was);

    // ldmatrix thread address components (row stride = 136 bf16 = 272 B, conflict-free)
    int sel = lane >> 3;
    uint aoff = ((sel & 1) * 8 + (lane & 7)) * 272 + (sel >> 1) * 16;  // A: i adds 16*272
    uint brow = (lane & 15);
    uint bcol = (uint)(gwarp * 32) * 2;                                // B col byte offset

    int gq = lane >> 2, tg = lane & 3;      // quad row g, quad thread t
    int cb = gwarp * 32 + tg * 2;           // thread's base column (j adds 8)

    const int NT = N_EDGES_C / 32;          // 10000
    int tid_g = tid & 127;
    int pe = tid_g >> 4, pg = tid_g & 15;

    int tile = blockIdx.x * 4 + group;
    uint4 pre[4];
    if (tile < NT) {
#pragma unroll
        for (int it = 0; it < 4; it++) {
            int e = pe + it * 8;
            pre[it] = *(const uint4*)&g_h[(size_t)(tile * 32 + e) * NH + pg * 8];
        }
    }

    for (; tile < NT; tile += GRID_P * 4) {
        int e0 = tile * 32;

        // ---- phase 1: BN + ReLU on prefetched hpre -> S (bf16) ----
#pragma unroll
        for (int it = 0; it < 4; it++) {
            int e = pe + it * 8;
            __nv_bfloat162* hp = (__nv_bfloat162*)&pre[it];
            int cc0 = pg * 8;
            uint4 outp;
            __nv_bfloat162* op = (__nv_bfloat162*)&outp;
#pragma unroll
            for (int q = 0; q < 4; q++) {
                float2 f = __bfloat1622float2(hp[q]);
                int c0 = cc0 + q * 2;
                float v0 = fmaxf(fmaf(f.x, p_bnA[c0 + 0], p_bnB[c0 + 0]), 0.f);
                float v1 = fmaxf(fmaf(f.y, p_bnA[c0 + 1], p_bnB[c0 + 1]), 0.f);
                op[q] = __floats2bfloat162_rn(v0, v1);
            }
            *(uint4*)&S[e * 136 + pg * 8] = outp;
        }
        {
            int ntile = tile + GRID_P * 4;
            if (ntile < NT) {
#pragma unroll
                for (int it = 0; it < 4; it++) {
                    int e = pe + it * 8;
                    pre[it] = *(const uint4*)&g_h[(size_t)(ntile * 32 + e) * NH + pg * 8];
                }
            }
        }
        BARG();

        // ---- phase 2: GEMM1 (S @ W2) in registers; epilogue: bias+ReLU -> S2, gate partials ----
        {
            float acc[2][4][4];
#pragma unroll
            for (int i = 0; i < 2; i++)
#pragma unroll
                for (int j = 0; j < 4; j++)
#pragma unroll
                    for (int r = 0; r < 4; r++) acc[i][j][r] = 0.f;
#pragma unroll
            for (int kk = 0; kk < 8; kk++) {
                uint a0[4], a1[4];
                ldsm_x4(a0[0], a0[1], a0[2], a0[3], sS + aoff + kk * 32);
                ldsm_x4(a1[0], a1[1], a1[2], a1[3], sS + aoff + 16 * 272 + kk * 32);
#pragma unroll
                for (int j = 0; j < 4; j++) {
                    uint b0, b1;
                    ldsm_x2t(b0, b1, sW2 + (kk * 16 + brow) * 272 + bcol + j * 16);
                    mma4(acc[0][j], a0, b0, b1);
                    mma4(acc[1][j], a1, b0, b1);
                }
            }
            float gpr[4] = {0.f, 0.f, 0.f, 0.f};   // rows g, g+8, 16+g, 24+g
#pragma unroll
            for (int i = 0; i < 2; i++) {
#pragma unroll
                for (int j = 0; j < 4; j++) {
                    int c0 = cb + j * 8;
                    float2 bb = *(const float2*)&p_b2[c0];
                    float2 wm = *(const float2*)&p_Wm[c0];
                    float v00 = fmaxf(acc[i][j][0] + bb.x, 0.f);
                    float v01 = fmaxf(acc[i][j][1] + bb.y, 0.f);
                    float v10 = fmaxf(acc[i][j][2] + bb.x, 0.f);
                    float v11 = fmaxf(acc[i][j][3] + bb.y, 0.f);
                    int r0 = i * 16 + gq;
                    __nv_bfloat162 p0 = __floats2bfloat162_rn(v00, v01);
                    __nv_bfloat162 p1 = __floats2bfloat162_rn(v10, v11);
                    *(__nv_bfloat162*)&S2[r0 * 136 + c0] = p0;
                    *(__nv_bfloat162*)&S2[(r0 + 8) * 136 + c0] = p1;
                    gpr[i * 2 + 0] = fmaf(v00, wm.x, fmaf(v01, wm.y, gpr[i * 2 + 0]));
                    gpr[i * 2 + 1] = fmaf(v10, wm.x, fmaf(v11, wm.y, gpr[i * 2 + 1]));
                }
            }
            // quad reduce gate partials, lane tg==0 writes
#pragma unroll
            for (int r = 0; r < 4; r++) {
                gpr[r] += __shfl_xor_sync(0xffffffffu, gpr[r], 1);
                gpr[r] += __shfl_xor_sync(0xffffffffu, gpr[r], 2);
            }
            if (tg == 0) {
                gp[(gq) * 4 + gwarp]      = gpr[0];
                gp[(gq + 8) * 4 + gwarp]  = gpr[1];
                gp[(gq + 16) * 4 + gwarp] = gpr[2];
                gp[(gq + 24) * 4 + gwarp] = gpr[3];
            }
        }
        BARG();

        // ---- phase 3: GEMM2 (S2 @ Wa); epilogue uses wg inline; s partials ----
        {
            float wgr[4];
#pragma unroll
            for (int r = 0; r < 4; r++) {
                int row = (r & 1) * 8 + (r >> 1) * 16 + gq;   // g, g+8, 16+g, 24+g order fix below
                (void)row;
            }
            // rows in order {gq, gq+8, gq+16, gq+24} mapped to wgr[0..3] as used in epilogue:
            {
                float4 q0 = *(const float4*)&gp[(gq) * 4];
                float4 q1 = *(const float4*)&gp[(gq + 8) * 4];
                float4 q2 = *(const float4*)&gp[(gq + 16) * 4];
                float4 q3 = *(const float4*)&gp[(gq + 24) * 4];
                wgr[0] = sigmoid_f(q0.x + q0.y + q0.z + q0.w + bmv);
                wgr[1] = sigmoid_f(q1.x + q1.y + q1.z + q1.w + bmv);
                wgr[2] = sigmoid_f(q2.x + q2.y + q2.z + q2.w + bmv);
                wgr[3] = sigmoid_f(q3.x + q3.y + q3.z + q3.w + bmv);
            }
            float acc[2][4][4];
#pragma unroll
            for (int i = 0; i < 2; i++)
#pragma unroll
                for (int j = 0; j < 4; j++)
#pragma unroll
                    for (int r = 0; r < 4; r++) acc[i][j][r] = 0.f;
#pragma unroll
            for (int kk = 0; kk < 8; kk++) {
                uint a0[4], a1[4];
                ldsm_x4(a0[0], a0[1], a0[2], a0[3], sS2 + aoff + kk * 32);
                ldsm_x4(a1[0], a1[1], a1[2], a1[3], sS2 + aoff + 16 * 272 + kk * 32);
#pragma unroll
                for (int j = 0; j < 4; j++) {
                    uint b0, b1;
                    ldsm_x2t(b0, b1, sWa + (kk * 16 + brow) * 272 + bcol + j * 16);
                    mma4(acc[0][j], a0, b0, b1);
                    mma4(acc[1][j], a1, b0, b1);
                }
            }
            float spr[4] = {0.f, 0.f, 0.f, 0.f};
#pragma unroll
            for (int i = 0; i < 2; i++) {
                float wg0 = wgr[i * 2 + 0];   // row i*16+gq
                float wg1 = wgr[i * 2 + 1];   // row i*16+gq+8
#pragma unroll
                for (int j = 0; j < 4; j++) {
                    int c0 = cb + j * 8;
                    float2 bav = *(const float2*)&p_ba[c0];
                    float2 wbv = *(const float2*)&p_Wb[c0];
                    float t00 = fmaxf(fmaf(wg0, acc[i][j][0], bav.x), 0.f);
                    float t01 = fmaxf(fmaf(wg0, acc[i][j][1], bav.y), 0.f);
                    float t10 = fmaxf(fmaf(wg1, acc[i][j][2], bav.x), 0.f);
                    float t11 = fmaxf(fmaf(wg1, acc[i][j][3], bav.y), 0.f);
                    spr[i * 2 + 0] = fmaf(t00, wbv.x, fmaf(t01, wbv.y, spr[i * 2 + 0]));
                    spr[i * 2 + 1] = fmaf(t10, wbv.x, fmaf(t11, wbv.y, spr[i * 2 + 1]));
                }
            }
#pragma unroll
            for (int r = 0; r < 4; r++) {
                spr[r] += __shfl_xor_sync(0xffffffffu, spr[r], 1);
                spr[r] += __shfl_xor_sync(0xffffffffu, spr[r], 2);
            }
            if (tg == 0) {
                sp[(gq) * 4 + gwarp]      = spr[0];
                sp[(gq + 8) * 4 + gwarp]  = spr[1];
                sp[(gq + 16) * 4 + gwarp] = spr[2];
                sp[(gq + 24) * 4 + gwarp] = spr[3];
            }
        }
        BARG();

        // ---- phase 4: finalize s (warp 0 of group); others proceed to next phase 1 ----
        if (gwarp == 0) {
            float4 q = *(const float4*)&sp[lane * 4];
            g_s[e0 + lane] = q.x + q.y + q.z + q.w;
        }
        // wgr[] mapping note: rows {gq,gq+8,gq+16,gq+24} == {i=0 r0, i=0 r1, i=1 r0, i=1 r1} ✓
    }
}

// ================= aggregation (slot order, 4-edge ILP; fused head; resets stats) =====
__global__ void __launch_bounds__(256)
k_agg(const float* __restrict__ xin, float* __restrict__ xout,
      int is_final,
      const float* __restrict__ We, const float* __restrict__ be,
      float* __restrict__ out) {
    if (blockIdx.x == 0 && threadIdx.x < 2 * NH) g_stats[threadIdx.x] = 0.f;
    int n = blockIdx.x * 8 + (threadIdx.x >> 5);
    if (n >= N_NODES_C) return;
    int lane = threadIdx.x & 31;
    float4 xi = *(const float4*)&xin[(size_t)n * NH + lane * 4];
    float4 acc = xi;
    int beg = g_rowptr[n], end = g_rowptr[n + 1];
    int j = beg;
    for (; j + 3 < end; j += 4) {
        float s0 = g_s[j], s1 = g_s[j + 1], s2 = g_s[j + 2], s3 = g_s[j + 3];
        int c0 = g_colj[j], c1 = g_colj[j + 1], c2 = g_colj[j + 2], c3 = g_colj[j + 3];
        float4 x0 = *(const float4*)&xin[(size_t)c0 * NH + lane * 4];
        float4 x1 = *(const float4*)&xin[(size_t)c1 * NH + lane * 4];
        float4 x2 = *(const float4*)&xin[(size_t)c2 * NH + lane * 4];
        float4 x3 = *(const float4*)&xin[(size_t)c3 * NH + lane * 4];
        acc.x += fminf(fmaxf((xi.x - x0.x) * s0, -100.f), 100.f)
               + fminf(fmaxf((xi.x - x1.x) * s1, -100.f), 100.f)
               + fminf(fmaxf((xi.x - x2.x) * s2, -100.f), 100.f)
               + fminf(fmaxf((xi.x - x3.x) * s3, -100.f), 100.f);
        acc.y += fminf(fmaxf((xi.y - x0.y) * s0, -100.f), 100.f)
               + fminf(fmaxf((xi.y - x1.y) * s1, -100.f), 100.f)
               + fminf(fmaxf((xi.y - x2.y) * s2, -100.f), 100.f)
               + fminf(fmaxf((xi.y - x3.y) * s3, -100.f), 100.f);
        acc.z += fminf(fmaxf((xi.z - x0.z) * s0, -100.f), 100.f)
               + fminf(fmaxf((xi.z - x1.z) * s1, -100.f), 100.f)
               + fminf(fmaxf((xi.z - x2.z) * s2, -100.f), 100.f)
               + fminf(fmaxf((xi.z - x3.z) * s3, -100.f), 100.f);
        acc.w += fminf(fmaxf((xi.w - x0.w) * s0, -100.f), 100.f)
               + fminf(fmaxf((xi.w - x1.w) * s1, -100.f), 100.f)
               + fminf(fmaxf((xi.w - x2.w) * s2, -100.f), 100.f)
               + fminf(fmaxf((xi.w - x3.w) * s3, -100.f), 100.f);
    }
    for (; j < end; j++) {
        float s = g_s[j];
        int c = g_colj[j];
        float4 xc = *(const float4*)&xin[(size_t)c * NH + lane * 4];
        acc.x += fminf(fmaxf((xi.x - xc.x) * s, -100.f), 100.f);
        acc.y += fminf(fmaxf((xi.y - xc.y) * s, -100.f), 100.f);
        acc.z += fminf(fmaxf((xi.z - xc.z) * s, -100.f), 100.f);
        acc.w += fminf(fmaxf((xi.w - xc.w) * s, -100.f), 100.f);
    }
    if (is_final) {
        int k0 = lane * 4;
        float p0 = acc.x * We[k0 * 2] + acc.y * We[(k0 + 1) * 2]
                 + acc.z * We[(k0 + 2) * 2] + acc.w * We[(k0 + 3) * 2];
        float p1 = acc.x * We[k0 * 2 + 1] + acc.y * We[(k0 + 1) * 2 + 1]
                 + acc.z * We[(k0 + 2) * 2 + 1] + acc.w * We[(k0 + 3) * 2 + 1];
#pragma unroll
        for (int o = 16; o; o >>= 1) {
            p0 += __shfl_xor_sync(0xffffffffu, p0, o);
            p1 += __shfl_xor_sync(0xffffffffu, p1, o);
        }
        if (lane == 0) {
            out[(size_t)n * 2 + 0] = sigmoid_f(p0 + be[0]);
            out[(size_t)n * 2 + 1] = sigmoid_f(p1 + be[1]);
        }
    } else {
        *(float4*)&xout[(size_t)n * NH + lane * 4] = acc;
    }
}

// ================= launch ==============================================================
extern "C" void kernel_launch(void* const* d_in, const int* in_sizes, int n_in,
                              void* d_out, int out_size) {
    (void)in_sizes; (void)n_in; (void)out_size;
    const float* x     = (const float*)d_in[0];
    const int*   ei    = (const int*)d_in[1];
    const float* ea    = (const float*)d_in[2];
    const float* W1    = (const float*)d_in[3];
    const float* gamma = (const float*)d_in[4];
    const float* beta  = (const float*)d_in[5];
    const float* W2    = (const float*)d_in[6];
    const float* b2    = (const float*)d_in[7];
    const float* Wa    = (const float*)d_in[8];
    const float* ba    = (const float*)d_in[9];
    const float* Wb    = (const float*)d_in[10];
    const float* Wm    = (const float*)d_in[11];
    const float* bm    = (const float*)d_in[12];
    const float* We    = (const float*)d_in[13];
    const float* be    = (const float*)d_in[14];
    float* out = (float*)d_out;

    const int smem_node  = 128 * 264 * 2 + 64 * 136 * 2;
    const int smem_fused = (2 * 128 * 136 + 2 * 4 * 32 * 136) * 2   // weights + S + S2 (bf16)
                         + (2 * 4 * 128 + 6 * 128) * 4;             // gp/sp + params
    cudaFuncSetAttribute(k_node,  cudaFuncAttributeMaxDynamicSharedMemorySize, smem_node);
    cudaFuncSetAttribute(k_fused, cudaFuncAttributeMaxDynamicSharedMemorySize, smem_fused);

    void *px = nullptr, *pcnt = nullptr, *pstats = nullptr, *px2 = nullptr;
    cudaGetSymbolAddress(&px, g_x);
    cudaGetSymbolAddress(&px2, g_x2);
    cudaGetSymbolAddress(&pcnt, g_cnt);
    cudaGetSymbolAddress(&pstats, g_stats);

    cudaMemcpyAsync(px, x, sizeof(float) * N_NODES_C * NH, cudaMemcpyDeviceToDevice, 0);
    cudaMemsetAsync(pcnt, 0, N_NODES_C * sizeof(int), 0);
    cudaMemsetAsync(pstats, 0, 2 * NH * sizeof(float), 0);

    k_hist<<<(N_EDGES_C + 255) / 256, 256>>>(ei);
    k_scan<<<1, 1024>>>();
    k_fillcsr<<<(N_EDGES_C + 255) / 256, 256>>>(ei);
    k_sortseg<<<(N_NODES_C + 7) / 8, 256>>>();
    k_perm<<<(N_EDGES_C + 255) / 256, 256>>>(ei, ea);

    float* bufA = (float*)px;
    float* bufB = (float*)px2;

    for (int l = 0; l < NLAYERS; l++) {
        const float* W1l = W1 + (size_t)l * DIN * NH;
        const float* xin  = (l & 1) ? bufB : bufA;
        float*       xout = (l & 1) ? bufA : bufB;
        int is_final = (l == NLAYERS - 1);
        k_node<<<GRID_P * 2, 256, smem_node>>>(xin, W1l);
        k_stats<<<1184, 256>>>(xin, W1l + 256 * NH);
        k_fused<<<GRID_P, 512, smem_fused>>>(gamma + l * NH, beta + l * NH,
                                             W2 + (size_t)l * NH * NH, b2 + l * NH,
                                             Wa + (size_t)l * NH * NH, ba + l * NH,
                                             Wb + l * NH,
                                             Wm + l * NH, bm + l);
        k_agg<<<(N_NODES_C + 7) / 8, 256>>>(xin, xout, is_final, We, be, out);
    }
}

// round 17
// speedup vs baseline: 1.4857x; 1.0919x over previous
#include <cuda_runtime.h>
#include <cuda_bf16.h>
#include <mma.h>
#include <math.h>

using namespace nvcuda;

#define N_NODES_C 20000
#define N_EDGES_C 320000
#define NH 128
#define DIN 262
#define NLAYERS 3
#define BN_EPS 1e-5f
#define GRID_P 148

typedef unsigned long long ull;
typedef unsigned int uint;

// ---------------- scratch ----------------
__device__ float g_x[N_NODES_C * NH];
__device__ float g_x2[N_NODES_C * NH];
__device__ float g_Y[(size_t)N_NODES_C * 256];              // [Y1 | Y2] per node
__device__ __nv_bfloat16 g_h[(size_t)N_EDGES_C * NH];       // hpre (bf16, slot order)
__device__ float g_s[N_EDGES_C];                            // per-slot phi_x scalar
__device__ float g_eap[N_EDGES_C * 4];                      // permuted edge_attr
__device__ int   g_colj[N_EDGES_C];                         // permuted col index
__device__ float g_stats[2 * NH];
__device__ int   g_cnt[N_NODES_C];
__device__ int   g_rowptr[N_NODES_C + 1];
__device__ int   g_eidx[N_EDGES_C];
__device__ int   g_ord[N_NODES_C];                          // nodes in ascending-degree order
__device__ __align__(16) __nv_bfloat16 g_W1h[NLAYERS * 128 * 264];   // k_node B images
__device__ __align__(16) __nv_bfloat16 g_Wh[2 * NLAYERS * 128 * 136]; // k_fused W2/Wa images

__device__ __forceinline__ float psi_f(float z) {
    return copysignf(log1pf(fabsf(z)), z);
}
__device__ __forceinline__ float sigmoid_f(float z) {
    return 1.0f / (1.0f + expf(-z));
}
__device__ __forceinline__ __nv_bfloat16 bf(float x) { return __float2bfloat16(x); }

// ---- packed fp32x2 helpers ----
__device__ __forceinline__ ull pk2(float lo, float hi) {
    ull r; asm("mov.b64 %0, {%1, %2};" : "=l"(r) : "f"(lo), "f"(hi)); return r;
}
__device__ __forceinline__ void upk2(ull v, float& lo, float& hi) {
    asm("mov.b64 {%0, %1}, %2;" : "=f"(lo), "=f"(hi) : "l"(v));
}
__device__ __forceinline__ ull fma2(ull a, ull b, ull c) {
    ull d; asm("fma.rn.f32x2 %0, %1, %2, %3;" : "=l"(d) : "l"(a), "l"(b), "l"(c)); return d;
}
__device__ __forceinline__ ull add2(ull a, ull b) {
    ull d; asm("add.rn.f32x2 %0, %1, %2;" : "=l"(d) : "l"(a), "l"(b)); return d;
}

// ---- raw mma.sync helpers (m16n8k16 bf16, row.col) ----
__device__ __forceinline__ void ldsm_x4(uint& r0, uint& r1, uint& r2, uint& r3, uint addr) {
    asm volatile("ldmatrix.sync.aligned.m8n8.x4.shared.b16 {%0,%1,%2,%3}, [%4];"
                 : "=r"(r0), "=r"(r1), "=r"(r2), "=r"(r3) : "r"(addr));
}
__device__ __forceinline__ void ldsm_x2t(uint& r0, uint& r1, uint addr) {
    asm volatile("ldmatrix.sync.aligned.m8n8.x2.trans.shared.b16 {%0,%1}, [%2];"
                 : "=r"(r0), "=r"(r1) : "r"(addr));
}
__device__ __forceinline__ void mma4(float* d, const uint* a, uint b0, uint b1) {
    asm volatile("mma.sync.aligned.m16n8k16.row.col.f32.bf16.bf16.f32 "
                 "{%0,%1,%2,%3},{%4,%5,%6,%7},{%8,%9},{%0,%1,%2,%3};"
                 : "+f"(d[0]), "+f"(d[1]), "+f"(d[2]), "+f"(d[3])
                 : "r"(a[0]), "r"(a[1]), "r"(a[2]), "r"(a[3]), "r"(b0), "r"(b1));
}

typedef wmma::fragment<wmma::matrix_a, 16, 16, 16, __nv_bfloat16, wmma::row_major> FragA;
typedef wmma::fragment<wmma::matrix_b, 16, 16, 16, __nv_bfloat16, wmma::row_major> FragB;
typedef wmma::fragment<wmma::accumulator, 16, 16, 16, float> FragC;

// ================= weight pre-conversion (once per launch) ===========================
__global__ void k_cvtw(const float* __restrict__ W1, const float* __restrict__ W2,
                       const float* __restrict__ Wa) {
    int i = blockIdx.x * 256 + threadIdx.x;
    const int tot1 = NLAYERS * 128 * 264;
    const int tot2 = NLAYERS * 128 * 136;
    if (i < tot1) {
        int l = i / (128 * 264);
        int rem = i - l * (128 * 264);
        int k = rem / 264, c = rem - k * 264;
        float v = 0.f;
        if (c < 128)       v = W1[(size_t)l * DIN * NH + (size_t)k * NH + c];
        else if (c < 256)  v = W1[(size_t)l * DIN * NH + (size_t)(128 + k) * NH + (c - 128)];
        g_W1h[i] = bf(v);
    } else if (i < tot1 + 2 * tot2) {
        int i2 = i - tot1;
        int w = i2 / tot2;
        int rem = i2 - w * tot2;
        int l = rem / (128 * 136);
        int r2 = rem - l * (128 * 136);
        int k = r2 / 136, c = r2 - k * 136;
        const float* W = w ? Wa : W2;
        float v = (c < 128) ? W[(size_t)l * NH * NH + (size_t)k * NH + c] : 0.f;
        g_Wh[i2] = bf(v);
    }
}

// ================= CSR build (once per launch) ========================================
__global__ void k_hist(const int* __restrict__ ei) {
    int e = blockIdx.x * 256 + threadIdx.x;
    if (e < N_EDGES_C) atomicAdd(&g_cnt[ei[e]], 1);
}

__global__ void k_scan() {
    __shared__ int part[1024];
    __shared__ int dh[256], dho[256], dcnt[256];
    int t = threadIdx.x;
    int base = t * 20;
    int s = 0;
    for (int i = 0; i < 20; i++) {
        int idx = base + i;
        if (idx < N_NODES_C) s += g_cnt[idx];
    }
    part[t] = s;
    __syncthreads();
    for (int off = 1; off < 1024; off <<= 1) {
        int v = (t >= off) ? part[t - off] : 0;
        __syncthreads();
        part[t] += v;
        __syncthreads();
    }
    int run = (t == 0) ? 0 : part[t - 1];
    for (int i = 0; i < 20; i++) {
        int idx = base + i;
        if (idx <= N_NODES_C) g_rowptr[idx] = run;
        if (idx < N_NODES_C) run += g_cnt[idx];
    }
    for (int i = 0; i < 20; i++) {
        int idx = base + i;
        if (idx < N_NODES_C) g_cnt[idx] = 0;
    }
    // ---- degree counting-sort -> g_ord (ascending degree) ----
    if (t < 256) { dh[t] = 0; dcnt[t] = 0; }
    __syncthreads();
    for (int i = 0; i < 20; i++) {
        int idx = base + i;
        if (idx < N_NODES_C) {
            int d = g_rowptr[idx + 1] - g_rowptr[idx];
            if (d > 255) d = 255;
            atomicAdd(&dh[d], 1);
        }
    }
    __syncthreads();
    if (t == 0) {
        int r = 0;
        for (int d = 0; d < 256; d++) { dho[d] = r; r += dh[d]; }
    }
    __syncthreads();
    for (int i = 0; i < 20; i++) {
        int idx = base + i;
        if (idx < N_NODES_C) {
            int d = g_rowptr[idx + 1] - g_rowptr[idx];
            if (d > 255) d = 255;
            int pos = dho[d] + atomicAdd(&dcnt[d], 1);
            g_ord[pos] = idx;
        }
    }
}

__global__ void k_fillcsr(const int* __restrict__ ei) {
    int e = blockIdx.x * 256 + threadIdx.x;
    if (e < N_EDGES_C) {
        int r = ei[e];
        int slot = g_rowptr[r] + atomicAdd(&g_cnt[r], 1);
        g_eidx[slot] = e;
    }
}

// sort each node's slot segment + emit permuted colj / edge_attr (merged kernel)
__global__ void k_sortperm(const int* __restrict__ ei, const float* __restrict__ ea) {
    int n = blockIdx.x * 8 + (threadIdx.x >> 5);
    if (n >= N_NODES_C) return;
    int lane = threadIdx.x & 31;
    int beg = g_rowptr[n], end = g_rowptr[n + 1];
    int d = end - beg;
    if (d > 1) {
        if (d <= 128) {
            int vals[4], ranks[4];
            int cnt = 0;
            for (int i = beg + lane; i < end; i += 32) vals[cnt++] = g_eidx[i];
            for (int tt = 0; tt < cnt; tt++) {
                int v = vals[tt], r = 0;
                for (int j = beg; j < end; j++) r += (g_eidx[j] < v);
                ranks[tt] = r;
            }
            __syncwarp();
            for (int tt = 0; tt < cnt; tt++) g_eidx[beg + ranks[tt]] = vals[tt];
        } else if (lane == 0) {
            for (int i = beg + 1; i < end; i++) {
                int v = g_eidx[i], j = i - 1;
                while (j >= beg && g_eidx[j] > v) { g_eidx[j + 1] = g_eidx[j]; j--; }
                g_eidx[j + 1] = v;
            }
        }
    }
    __syncwarp();
    for (int j = beg + lane; j < end; j += 32) {
        int e = g_eidx[j];
        g_colj[j] = ei[N_EDGES_C + e];
        *(float4*)&g_eap[(size_t)j * 4] = *(const float4*)&ea[(size_t)e * 4];
    }
}

// ================= node GEMM: Y = X @ [W1a | W1b] (2 CTAs/SM, preconverted B) =========
__global__ void __launch_bounds__(256, 2)
k_node(const float* __restrict__ xin, int l) {
    extern __shared__ __align__(16) char smraw[];
    __nv_bfloat16* Bs = (__nv_bfloat16*)smraw;        // 128 x 264
    __nv_bfloat16* As = Bs + 128 * 264;               // 64 x 136

    int tid = threadIdx.x;
    int warp = tid >> 5;
    int wy = warp >> 2, wx = warp & 3;

    const uint4* wsrc = (const uint4*)(g_W1h + (size_t)l * 128 * 264);
    for (int idx = tid; idx < 128 * 264 / 8; idx += 256)
        ((uint4*)Bs)[idx] = wsrc[idx];

    const int NT = (N_NODES_C + 63) / 64;   // 313
    for (int tile = blockIdx.x; tile < NT; tile += GRID_P * 2) {
        int n0 = tile * 64;
        __syncthreads();
        for (int idx = tid; idx < 64 * 32; idx += 256) {
            int e = idx >> 5, g = idx & 31;
            int r = n0 + e; if (r >= N_NODES_C) r = N_NODES_C - 1;
            float4 v = *(const float4*)&xin[(size_t)r * NH + g * 4];
            __nv_bfloat16* dst = &As[e * 136 + g * 4];
            dst[0] = bf(v.x); dst[1] = bf(v.y); dst[2] = bf(v.z); dst[3] = bf(v.w);
        }
        __syncthreads();

        FragC acc[2][4];
#pragma unroll
        for (int i = 0; i < 2; i++)
#pragma unroll
            for (int j = 0; j < 4; j++) wmma::fill_fragment(acc[i][j], 0.f);

#pragma unroll
        for (int kk = 0; kk < NH; kk += 16) {
            FragA a0, a1;
            wmma::load_matrix_sync(a0, &As[(wy * 32) * 136 + kk], 136);
            wmma::load_matrix_sync(a1, &As[(wy * 32 + 16) * 136 + kk], 136);
#pragma unroll
            for (int j = 0; j < 4; j++) {
                FragB bfr;
                wmma::load_matrix_sync(bfr, &Bs[kk * 264 + wx * 64 + j * 16], 264);
                wmma::mma_sync(acc[0][j], a0, bfr, acc[0][j]);
                wmma::mma_sync(acc[1][j], a1, bfr, acc[1][j]);
            }
        }
#pragma unroll
        for (int i = 0; i < 2; i++) {
            int row0 = n0 + wy * 32 + i * 16;
            if (row0 + 16 <= N_NODES_C) {
#pragma unroll
                for (int j = 0; j < 4; j++)
                    wmma::store_matrix_sync(&g_Y[(size_t)row0 * 256 + wx * 64 + j * 16],
                                            acc[i][j], 256, wmma::mem_row_major);
            }
        }
    }
}

// ================= stats pass: warp-per-node (degree-balanced), 2-edge ILP, f32x2 =====
__global__ void __launch_bounds__(256)
k_stats(const float* __restrict__ xin, const float* __restrict__ W1c) {
    __shared__ __align__(16) float w1c[6 * 128];
    __shared__ float red[2 * 128];

    int tid = threadIdx.x;
    int warp = tid >> 5, lane = tid & 31;
    for (int i = tid; i < 6 * 128; i += 256) w1c[i] = W1c[i];
    if (tid < 256) red[tid] = 0.f;
    __syncthreads();

    int col = lane * 4;
    float sgn0 = (lane == 0) ? 1.f : -1.f;

    ull as0 = 0, as1 = 0, aq0 = 0, aq1 = 0;
    const ull* w64 = (const ull*)w1c;

    int gw = blockIdx.x * 8 + warp;
    int tw = gridDim.x * 8;
    for (int kidx = gw; kidx < N_NODES_C; kidx += tw) {
        int n = g_ord[N_NODES_C - 1 - kidx];   // descending degree (LPT balance)
        float4 xr = *(const float4*)&xin[(size_t)n * NH + col];
        float4 y1 = *(const float4*)&g_Y[(size_t)n * 256 + col];
        ull hbp0 = pk2(y1.x, y1.y);
        ull hbp1 = pk2(y1.z, y1.w);
        int beg = g_rowptr[n], end = g_rowptr[n + 1];
        int j = beg;

        for (; j + 1 < end; j += 2) {
            int c0 = g_colj[j];
            int c1 = g_colj[j + 1];
            float4 xc0 = *(const float4*)&xin[(size_t)c0 * NH + col];
            float4 xc1 = *(const float4*)&xin[(size_t)c1 * NH + col];
            float4 y20 = *(const float4*)&g_Y[(size_t)c0 * 256 + 128 + col];
            float4 y21 = *(const float4*)&g_Y[(size_t)c1 * 256 + 128 + col];
            float4 ev0 = *(const float4*)&g_eap[(size_t)j * 4];
            float4 ev1 = *(const float4*)&g_eap[(size_t)(j + 1) * 4];

            float d0x = xr.x - xc0.x, d0y = xr.y - xc0.y, d0z = xr.z - xc0.z, d0w = xr.w - xc0.w;
            float d1x = xr.x - xc1.x, d1y = xr.y - xc1.y, d1z = xr.z - xc1.z, d1w = xr.w - xc1.w;
            float dd0 = sgn0 * d0x * d0x - d0y * d0y - d0z * d0z - d0w * d0w;
            float ij0 = sgn0 * xr.x * xc0.x - xr.y * xc0.y - xr.z * xc0.z - xr.w * xc0.w;
            float dd1 = sgn0 * d1x * d1x - d1y * d1y - d1z * d1z - d1w * d1w;
            float ij1 = sgn0 * xr.x * xc1.x - xr.y * xc1.y - xr.z * xc1.z - xr.w * xc1.w;
#pragma unroll
            for (int o = 16; o; o >>= 1) {
                dd0 += __shfl_xor_sync(0xffffffffu, dd0, o);
                ij0 += __shfl_xor_sync(0xffffffffu, ij0, o);
                dd1 += __shfl_xor_sync(0xffffffffu, dd1, o);
                ij1 += __shfl_xor_sync(0xffffffffu, ij1, o);
            }
            float nrm0 = psi_f(dd0), dt0 = psi_f(ij0);
            float nrm1 = psi_f(dd1), dt1 = psi_f(ij1);

            ull w0a = w64[(0 * 128 + col) >> 1], w0b = w64[(0 * 128 + col + 2) >> 1];
            ull w1a = w64[(1 * 128 + col) >> 1], w1b = w64[(1 * 128 + col + 2) >> 1];
            ull w2a = w64[(2 * 128 + col) >> 1], w2b = w64[(2 * 128 + col + 2) >> 1];
            ull w3a = w64[(3 * 128 + col) >> 1], w3b = w64[(3 * 128 + col + 2) >> 1];
            ull w4a = w64[(4 * 128 + col) >> 1], w4b = w64[(4 * 128 + col + 2) >> 1];
            ull w5a = w64[(5 * 128 + col) >> 1], w5b = w64[(5 * 128 + col + 2) >> 1];

            {
                ull ex = pk2(ev0.x, ev0.x), ey = pk2(ev0.y, ev0.y);
                ull ez = pk2(ev0.z, ev0.z), ew = pk2(ev0.w, ev0.w);
                ull en = pk2(nrm0, nrm0),   et = pk2(dt0, dt0);
                ull h0 = add2(hbp0, pk2(y20.x, y20.y));
                ull h1 = add2(hbp1, pk2(y20.z, y20.w));
                h0 = fma2(ex, w0a, h0);  h1 = fma2(ex, w0b, h1);
                h0 = fma2(ey, w1a, h0);  h1 = fma2(ey, w1b, h1);
                h0 = fma2(ez, w2a, h0);  h1 = fma2(ez, w2b, h1);
                h0 = fma2(ew, w3a, h0);  h1 = fma2(ew, w3b, h1);
                h0 = fma2(en, w4a, h0);  h1 = fma2(en, w4b, h1);
                h0 = fma2(et, w5a, h0);  h1 = fma2(et, w5b, h1);
                as0 = add2(as0, h0);  as1 = add2(as1, h1);
                aq0 = fma2(h0, h0, aq0);  aq1 = fma2(h1, h1, aq1);
                float f0, f1, f2, f3;
                upk2(h0, f0, f1); upk2(h1, f2, f3);
                __nv_bfloat162 a = __floats2bfloat162_rn(f0, f1);
                __nv_bfloat162 b = __floats2bfloat162_rn(f2, f3);
                uint2 pk; pk.x = *(unsigned int*)&a; pk.y = *(unsigned int*)&b;
                *(uint2*)&g_h[(size_t)j * NH + col] = pk;
            }
            {
                ull ex = pk2(ev1.x, ev1.x), ey = pk2(ev1.y, ev1.y);
                ull ez = pk2(ev1.z, ev1.z), ew = pk2(ev1.w, ev1.w);
                ull en = pk2(nrm1, nrm1),   et = pk2(dt1, dt1);
                ull h0 = add2(hbp0, pk2(y21.x, y21.y));
                ull h1 = add2(hbp1, pk2(y21.z, y21.w));
                h0 = fma2(ex, w0a, h0);  h1 = fma2(ex, w0b, h1);
                h0 = fma2(ey, w1a, h0);  h1 = fma2(ey, w1b, h1);
                h0 = fma2(ez, w2a, h0);  h1 = fma2(ez, w2b, h1);
                h0 = fma2(ew, w3a, h0);  h1 = fma2(ew, w3b, h1);
                h0 = fma2(en, w4a, h0);  h1 = fma2(en, w4b, h1);
                h0 = fma2(et, w5a, h0);  h1 = fma2(et, w5b, h1);
                as0 = add2(as0, h0);  as1 = add2(as1, h1);
                aq0 = fma2(h0, h0, aq0);  aq1 = fma2(h1, h1, aq1);
                float f0, f1, f2, f3;
                upk2(h0, f0, f1); upk2(h1, f2, f3);
                __nv_bfloat162 a = __floats2bfloat162_rn(f0, f1);
                __nv_bfloat162 b = __floats2bfloat162_rn(f2, f3);
                uint2 pk; pk.x = *(unsigned int*)&a; pk.y = *(unsigned int*)&b;
                *(uint2*)&g_h[(size_t)(j + 1) * NH + col] = pk;
            }
        }

        if (j < end) {
            int c = g_colj[j];
            float4 xc = *(const float4*)&xin[(size_t)c * NH + col];
            float4 y2 = *(const float4*)&g_Y[(size_t)c * 256 + 128 + col];
            float dx = xr.x - xc.x, dy = xr.y - xc.y, dz = xr.z - xc.z, dw = xr.w - xc.w;
            float dd = sgn0 * dx * dx - dy * dy - dz * dz - dw * dw;
            float ij = sgn0 * xr.x * xc.x - xr.y * xc.y - xr.z * xc.z - xr.w * xc.w;
#pragma unroll
            for (int o = 16; o; o >>= 1) {
                dd += __shfl_xor_sync(0xffffffffu, dd, o);
                ij += __shfl_xor_sync(0xffffffffu, ij, o);
            }
            float nrm = psi_f(dd), dt = psi_f(ij);
            float4 eav = *(const float4*)&g_eap[(size_t)j * 4];
            ull ex = pk2(eav.x, eav.x), ey = pk2(eav.y, eav.y);
            ull ez = pk2(eav.z, eav.z), ew = pk2(eav.w, eav.w);
            ull en = pk2(nrm, nrm),     et = pk2(dt, dt);
            ull h0 = add2(hbp0, pk2(y2.x, y2.y));
            ull h1 = add2(hbp1, pk2(y2.z, y2.w));
            h0 = fma2(ex, w64[(0 * 128 + col) >> 1], h0);  h1 = fma2(ex, w64[(0 * 128 + col + 2) >> 1], h1);
            h0 = fma2(ey, w64[(1 * 128 + col) >> 1], h0);  h1 = fma2(ey, w64[(1 * 128 + col + 2) >> 1], h1);
            h0 = fma2(ez, w64[(2 * 128 + col) >> 1], h0);  h1 = fma2(ez, w64[(2 * 128 + col + 2) >> 1], h1);
            h0 = fma2(ew, w64[(3 * 128 + col) >> 1], h0);  h1 = fma2(ew, w64[(3 * 128 + col + 2) >> 1], h1);
            h0 = fma2(en, w64[(4 * 128 + col) >> 1], h0);  h1 = fma2(en, w64[(4 * 128 + col + 2) >> 1], h1);
            h0 = fma2(et, w64[(5 * 128 + col) >> 1], h0);  h1 = fma2(et, w64[(5 * 128 + col + 2) >> 1], h1);
            as0 = add2(as0, h0);  as1 = add2(as1, h1);
            aq0 = fma2(h0, h0, aq0);  aq1 = fma2(h1, h1, aq1);
            float f0, f1, f2, f3;
            upk2(h0, f0, f1); upk2(h1, f2, f3);
            __nv_bfloat162 a = __floats2bfloat162_rn(f0, f1);
            __nv_bfloat162 b = __floats2bfloat162_rn(f2, f3);
            uint2 pk; pk.x = *(unsigned int*)&a; pk.y = *(unsigned int*)&b;
            *(uint2*)&g_h[(size_t)j * NH + col] = pk;
        }
    }

    {
        float s0, s1, s2, s3, q0, q1, q2, q3;
        upk2(as0, s0, s1); upk2(as1, s2, s3);
        upk2(aq0, q0, q1); upk2(aq1, q2, q3);
        atomicAdd(&red[col + 0], s0); atomicAdd(&red[col + 1], s1);
        atomicAdd(&red[col + 2], s2); atomicAdd(&red[col + 3], s3);
        atomicAdd(&red[128 + col + 0], q0); atomicAdd(&red[128 + col + 1], q1);
        atomicAdd(&red[128 + col + 2], q2); atomicAdd(&red[128 + col + 3], q3);
    }
    __syncthreads();
    if (tid < 256) atomicAdd(&g_stats[tid], red[tid]);
}

// ================= fused edge MLP v2: raw mma.sync, register epilogues ================
#define BARG() asm volatile("bar.sync %0, 128;" :: "r"(group + 1) : "memory")

__global__ void __launch_bounds__(512, 1)
k_fused(const float* __restrict__ gamma, const float* __restrict__ beta,
        int l, const float* __restrict__ b2,
        const float* __restrict__ ba,
        const float* __restrict__ Wb,
        const float* __restrict__ Wm, const float* __restrict__ bm) {
    extern __shared__ __align__(16) char smraw[];
    __nv_bfloat16* W2s  = (__nv_bfloat16*)smraw;      // 128 x 136
    __nv_bfloat16* Was  = W2s + 128 * 136;            // 128 x 136
    __nv_bfloat16* Sall = Was + 128 * 136;            // 4 x (32 x 136)
    __nv_bfloat16* S2all = Sall + 4 * 32 * 136;       // 4 x (32 x 136)
    float* gp_all = (float*)(S2all + 4 * 32 * 136);   // 4 x 128
    float* sp_all = gp_all + 4 * 128;                 // 4 x 128
    float* p_bnA = sp_all + 4 * 128;
    float* p_bnB = p_bnA + NH;
    float* p_b2  = p_bnB + NH;
    float* p_ba  = p_b2 + NH;
    float* p_Wm  = p_ba + NH;
    float* p_Wb  = p_Wm + NH;

    int tid = threadIdx.x;
    int warp = tid >> 5, lane = tid & 31;
    int group = warp >> 2;                 // 0..3
    int gwarp = warp & 3;                  // column quarter
    float bmv = bm[0];

    __nv_bfloat16* S  = Sall + group * 32 * 136;
    __nv_bfloat16* S2 = S2all + group * 32 * 136;
    float* gp = gp_all + group * 128;
    float* sp = sp_all + group * 128;

    {
        const uint4* w2src = (const uint4*)(g_Wh + (size_t)(0 * NLAYERS + l) * 128 * 136);
        const uint4* wasrc = (const uint4*)(g_Wh + (size_t)(1 * NLAYERS + l) * 128 * 136);
        for (int idx = tid; idx < 128 * 136 / 8; idx += 512) {
            ((uint4*)W2s)[idx] = w2src[idx];
            ((uint4*)Was)[idx] = wasrc[idx];
        }
    }
    if (tid < NH) {
        float inv = 1.f / (float)N_EDGES_C;
        float mean = g_stats[tid] * inv;
        float var = g_stats[NH + tid] * inv - mean * mean;
        float sc = gamma[tid] * rsqrtf(var + BN_EPS);
        p_bnA[tid] = sc;
        p_bnB[tid] = beta[tid] - mean * sc;
        p_b2[tid]  = b2[tid];
        p_ba[tid]  = ba[tid];
        p_Wm[tid]  = Wm[tid];
        p_Wb[tid]  = Wb[tid];
    }
    __syncthreads();

    uint sS  = (uint)__cvta_generic_to_shared(S);
    uint sS2 = (uint)__cvta_generic_to_shared(S2);
    uint sW2 = (uint)__cvta_generic_to_shared(W2s);
    uint sWa = (uint)__cvta_generic_to_shared(Was);

    int sel = lane >> 3;
    uint aoff = ((sel & 1) * 8 + (lane & 7)) * 272 + (sel >> 1) * 16;
    uint brow = (lane & 15);
    uint bcol = (uint)(gwarp * 32) * 2;

    int gq = lane >> 2, tg = lane & 3;
    int cb = gwarp * 32 + tg * 2;

    const int NT = N_EDGES_C / 32;          // 10000
    int tid_g = tid & 127;
    int pe = tid_g >> 4, pg = tid_g & 15;

    int tile = blockIdx.x * 4 + group;
    uint4 pre[4];
    if (tile < NT) {
#pragma unroll
        for (int it = 0; it < 4; it++) {
            int e = pe + it * 8;
            pre[it] = *(const uint4*)&g_h[(size_t)(tile * 32 + e) * NH + pg * 8];
        }
    }

    for (; tile < NT; tile += GRID_P * 4) {
        int e0 = tile * 32;

        // ---- phase 1: BN + ReLU on prefetched hpre -> S (bf16) ----
#pragma unroll
        for (int it = 0; it < 4; it++) {
            int e = pe + it * 8;
            __nv_bfloat162* hp = (__nv_bfloat162*)&pre[it];
            int cc0 = pg * 8;
            uint4 outp;
            __nv_bfloat162* op = (__nv_bfloat162*)&outp;
#pragma unroll
            for (int q = 0; q < 4; q++) {
                float2 f = __bfloat1622float2(hp[q]);
                int c0 = cc0 + q * 2;
                float v0 = fmaxf(fmaf(f.x, p_bnA[c0 + 0], p_bnB[c0 + 0]), 0.f);
                float v1 = fmaxf(fmaf(f.y, p_bnA[c0 + 1], p_bnB[c0 + 1]), 0.f);
                op[q] = __floats2bfloat162_rn(v0, v1);
            }
            *(uint4*)&S[e * 136 + pg * 8] = outp;
        }
        {
            int ntile = tile + GRID_P * 4;
            if (ntile < NT) {
#pragma unroll
                for (int it = 0; it < 4; it++) {
                    int e = pe + it * 8;
                    pre[it] = *(const uint4*)&g_h[(size_t)(ntile * 32 + e) * NH + pg * 8];
                }
            }
        }
        BARG();

        // ---- phase 2: GEMM1 (S @ W2); epilogue: bias+ReLU -> S2, gate partials ----
        {
            float acc[2][4][4];
#pragma unroll
            for (int i = 0; i < 2; i++)
#pragma unroll
                for (int j = 0; j < 4; j++)
#pragma unroll
                    for (int r = 0; r < 4; r++) acc[i][j][r] = 0.f;
#pragma unroll
            for (int kk = 0; kk < 8; kk++) {
                uint a0[4], a1[4];
                ldsm_x4(a0[0], a0[1], a0[2], a0[3], sS + aoff + kk * 32);
                ldsm_x4(a1[0], a1[1], a1[2], a1[3], sS + aoff + 16 * 272 + kk * 32);
#pragma unroll
                for (int j = 0; j < 4; j++) {
                    uint b0, b1;
                    ldsm_x2t(b0, b1, sW2 + (kk * 16 + brow) * 272 + bcol + j * 16);
                    mma4(acc[0][j], a0, b0, b1);
                    mma4(acc[1][j], a1, b0, b1);
                }
            }
            float gpr[4] = {0.f, 0.f, 0.f, 0.f};
#pragma unroll
            for (int i = 0; i < 2; i++) {
#pragma unroll
                for (int j = 0; j < 4; j++) {
                    int c0 = cb + j * 8;
                    float2 bb = *(const float2*)&p_b2[c0];
                    float2 wm = *(const float2*)&p_Wm[c0];
                    float v00 = fmaxf(acc[i][j][0] + bb.x, 0.f);
                    float v01 = fmaxf(acc[i][j][1] + bb.y, 0.f);
                    float v10 = fmaxf(acc[i][j][2] + bb.x, 0.f);
                    float v11 = fmaxf(acc[i][j][3] + bb.y, 0.f);
                    int r0 = i * 16 + gq;
                    __nv_bfloat162 p0 = __floats2bfloat162_rn(v00, v01);
                    __nv_bfloat162 p1 = __floats2bfloat162_rn(v10, v11);
                    *(__nv_bfloat162*)&S2[r0 * 136 + c0] = p0;
                    *(__nv_bfloat162*)&S2[(r0 + 8) * 136 + c0] = p1;
                    gpr[i * 2 + 0] = fmaf(v00, wm.x, fmaf(v01, wm.y, gpr[i * 2 + 0]));
                    gpr[i * 2 + 1] = fmaf(v10, wm.x, fmaf(v11, wm.y, gpr[i * 2 + 1]));
                }
            }
#pragma unroll
            for (int r = 0; r < 4; r++) {
                gpr[r] += __shfl_xor_sync(0xffffffffu, gpr[r], 1);
                gpr[r] += __shfl_xor_sync(0xffffffffu, gpr[r], 2);
            }
            if (tg == 0) {
                gp[(gq) * 4 + gwarp]      = gpr[0];
                gp[(gq + 8) * 4 + gwarp]  = gpr[1];
                gp[(gq + 16) * 4 + gwarp] = gpr[2];
                gp[(gq + 24) * 4 + gwarp] = gpr[3];
            }
        }
        BARG();

        // ---- phase 3: GEMM2 (S2 @ Wa); wg inline; s partials ----
        {
            float wgr[4];
            {
                float4 q0 = *(const float4*)&gp[(gq) * 4];
                float4 q1 = *(const float4*)&gp[(gq + 8) * 4];
                float4 q2 = *(const float4*)&gp[(gq + 16) * 4];
                float4 q3 = *(const float4*)&gp[(gq + 24) * 4];
                wgr[0] = sigmoid_f(q0.x + q0.y + q0.z + q0.w + bmv);
                wgr[1] = sigmoid_f(q1.x + q1.y + q1.z + q1.w + bmv);
                wgr[2] = sigmoid_f(q2.x + q2.y + q2.z + q2.w + bmv);
                wgr[3] = sigmoid_f(q3.x + q3.y + q3.z + q3.w + bmv);
            }
            float acc[2][4][4];
#pragma unroll
            for (int i = 0; i < 2; i++)
#pragma unroll
                for (int j = 0; j < 4; j++)
#pragma unroll
                    for (int r = 0; r < 4; r++) acc[i][j][r] = 0.f;
#pragma unroll
            for (int kk = 0; kk < 8; kk++) {
                uint a0[4], a1[4];
                ldsm_x4(a0[0], a0[1], a0[2], a0[3], sS2 + aoff + kk * 32);
                ldsm_x4(a1[0], a1[1], a1[2], a1[3], sS2 + aoff + 16 * 272 + kk * 32);
#pragma unroll
                for (int j = 0; j < 4; j++) {
                    uint b0, b1;
                    ldsm_x2t(b0, b1, sWa + (kk * 16 + brow) * 272 + bcol + j * 16);
                    mma4(acc[0][j], a0, b0, b1);
                    mma4(acc[1][j], a1, b0, b1);
                }
            }
            float spr[4] = {0.f, 0.f, 0.f, 0.f};
#pragma unroll
            for (int i = 0; i < 2; i++) {
                float wg0 = wgr[i * 2 + 0];
                float wg1 = wgr[i * 2 + 1];
#pragma unroll
                for (int j = 0; j < 4; j++) {
                    int c0 = cb + j * 8;
                    float2 bav = *(const float2*)&p_ba[c0];
                    float2 wbv = *(const float2*)&p_Wb[c0];
                    float t00 = fmaxf(fmaf(wg0, acc[i][j][0], bav.x), 0.f);
                    float t01 = fmaxf(fmaf(wg0, acc[i][j][1], bav.y), 0.f);
                    float t10 = fmaxf(fmaf(wg1, acc[i][j][2], bav.x), 0.f);
                    float t11 = fmaxf(fmaf(wg1, acc[i][j][3], bav.y), 0.f);
                    spr[i * 2 + 0] = fmaf(t00, wbv.x, fmaf(t01, wbv.y, spr[i * 2 + 0]));
                    spr[i * 2 + 1] = fmaf(t10, wbv.x, fmaf(t11, wbv.y, spr[i * 2 + 1]));
                }
            }
#pragma unroll
            for (int r = 0; r < 4; r++) {
                spr[r] += __shfl_xor_sync(0xffffffffu, spr[r], 1);
                spr[r] += __shfl_xor_sync(0xffffffffu, spr[r], 2);
            }
            if (tg == 0) {
                sp[(gq) * 4 + gwarp]      = spr[0];
                sp[(gq + 8) * 4 + gwarp]  = spr[1];
                sp[(gq + 16) * 4 + gwarp] = spr[2];
                sp[(gq + 24) * 4 + gwarp] = spr[3];
            }
        }
        BARG();

        // ---- phase 4: finalize s (warp 0 of group) ----
        if (gwarp == 0) {
            float4 q = *(const float4*)&sp[lane * 4];
            g_s[e0 + lane] = q.x + q.y + q.z + q.w;
        }
    }
}

// ================= aggregation (degree-balanced, 4-edge ILP; head; stats reset) =======
__global__ void __launch_bounds__(256)
k_agg(const float* __restrict__ xin, float* __restrict__ xout,
      int is_final,
      const float* __restrict__ We, const float* __restrict__ be,
      float* __restrict__ out) {
    if (blockIdx.x == 0 && threadIdx.x < 2 * NH) g_stats[threadIdx.x] = 0.f;
    int n0 = blockIdx.x * 8 + (threadIdx.x >> 5);
    if (n0 >= N_NODES_C) return;
    int n = g_ord[N_NODES_C - 1 - n0];
    int lane = threadIdx.x & 31;
    float4 xi = *(const float4*)&xin[(size_t)n * NH + lane * 4];
    float4 acc = xi;
    int beg = g_rowptr[n], end = g_rowptr[n + 1];
    int j = beg;
    for (; j + 3 < end; j += 4) {
        float s0 = g_s[j], s1 = g_s[j + 1], s2 = g_s[j + 2], s3 = g_s[j + 3];
        int c0 = g_colj[j], c1 = g_colj[j + 1], c2 = g_colj[j + 2], c3 = g_colj[j + 3];
        float4 x0 = *(const float4*)&xin[(size_t)c0 * NH + lane * 4];
        float4 x1 = *(const float4*)&xin[(size_t)c1 * NH + lane * 4];
        float4 x2 = *(const float4*)&xin[(size_t)c2 * NH + lane * 4];
        float4 x3 = *(const float4*)&xin[(size_t)c3 * NH + lane * 4];
        acc.x += fminf(fmaxf((xi.x - x0.x) * s0, -100.f), 100.f)
               + fminf(fmaxf((xi.x - x1.x) * s1, -100.f), 100.f)
               + fminf(fmaxf((xi.x - x2.x) * s2, -100.f), 100.f)
               + fminf(fmaxf((xi.x - x3.x) * s3, -100.f), 100.f);
        acc.y += fminf(fmaxf((xi.y - x0.y) * s0, -100.f), 100.f)
               + fminf(fmaxf((xi.y - x1.y) * s1, -100.f), 100.f)
               + fminf(fmaxf((xi.y - x2.y) * s2, -100.f), 100.f)
               + fminf(fmaxf((xi.y - x3.y) * s3, -100.f), 100.f);
        acc.z += fminf(fmaxf((xi.z - x0.z) * s0, -100.f), 100.f)
               + fminf(fmaxf((xi.z - x1.z) * s1, -100.f), 100.f)
               + fminf(fmaxf((xi.z - x2.z) * s2, -100.f), 100.f)
               + fminf(fmaxf((xi.z - x3.z) * s3, -100.f), 100.f);
        acc.w += fminf(fmaxf((xi.w - x0.w) * s0, -100.f), 100.f)
               + fminf(fmaxf((xi.w - x1.w) * s1, -100.f), 100.f)
               + fminf(fmaxf((xi.w - x2.w) * s2, -100.f), 100.f)
               + fminf(fmaxf((xi.w - x3.w) * s3, -100.f), 100.f);
    }
    for (; j < end; j++) {
        float s = g_s[j];
        int c = g_colj[j];
        float4 xc = *(const float4*)&xin[(size_t)c * NH + lane * 4];
        acc.x += fminf(fmaxf((xi.x - xc.x) * s, -100.f), 100.f);
        acc.y += fminf(fmaxf((xi.y - xc.y) * s, -100.f), 100.f);
        acc.z += fminf(fmaxf((xi.z - xc.z) * s, -100.f), 100.f);
        acc.w += fminf(fmaxf((xi.w - xc.w) * s, -100.f), 100.f);
    }
    if (is_final) {
        int k0 = lane * 4;
        float p0 = acc.x * We[k0 * 2] + acc.y * We[(k0 + 1) * 2]
                 + acc.z * We[(k0 + 2) * 2] + acc.w * We[(k0 + 3) * 2];
        float p1 = acc.x * We[k0 * 2 + 1] + acc.y * We[(k0 + 1) * 2 + 1]
                 + acc.z * We[(k0 + 2) * 2 + 1] + acc.w * We[(k0 + 3) * 2 + 1];
#pragma unroll
        for (int o = 16; o; o >>= 1) {
            p0 += __shfl_xor_sync(0xffffffffu, p0, o);
            p1 += __shfl_xor_sync(0xffffffffu, p1, o);
        }
        if (lane == 0) {
            out[(size_t)n * 2 + 0] = sigmoid_f(p0 + be[0]);
            out[(size_t)n * 2 + 1] = sigmoid_f(p1 + be[1]);
        }
    } else {
        *(float4*)&xout[(size_t)n * NH + lane * 4] = acc;
    }
}

// ================= launch ==============================================================
extern "C" void kernel_launch(void* const* d_in, const int* in_sizes, int n_in,
                              void* d_out, int out_size) {
    (void)in_sizes; (void)n_in; (void)out_size;
    const float* x     = (const float*)d_in[0];
    const int*   ei    = (const int*)d_in[1];
    const float* ea    = (const float*)d_in[2];
    const float* W1    = (const float*)d_in[3];
    const float* gamma = (const float*)d_in[4];
    const float* beta  = (const float*)d_in[5];
    const float* W2    = (const float*)d_in[6];
    const float* b2    = (const float*)d_in[7];
    const float* Wa    = (const float*)d_in[8];
    const float* ba    = (const float*)d_in[9];
    const float* Wb    = (const float*)d_in[10];
    const float* Wm    = (const float*)d_in[11];
    const float* bm    = (const float*)d_in[12];
    const float* We    = (const float*)d_in[13];
    const float* be    = (const float*)d_in[14];
    float* out = (float*)d_out;

    const int smem_node  = 128 * 264 * 2 + 64 * 136 * 2;
    const int smem_fused = (2 * 128 * 136 + 2 * 4 * 32 * 136) * 2
                         + (2 * 4 * 128 + 6 * 128) * 4;
    cudaFuncSetAttribute(k_node,  cudaFuncAttributeMaxDynamicSharedMemorySize, smem_node);
    cudaFuncSetAttribute(k_fused, cudaFuncAttributeMaxDynamicSharedMemorySize, smem_fused);

    void *px = nullptr, *pcnt = nullptr, *pstats = nullptr, *px2 = nullptr;
    cudaGetSymbolAddress(&px, g_x);
    cudaGetSymbolAddress(&px2, g_x2);
    cudaGetSymbolAddress(&pcnt, g_cnt);
    cudaGetSymbolAddress(&pstats, g_stats);

    cudaMemcpyAsync(px, x, sizeof(float) * N_NODES_C * NH, cudaMemcpyDeviceToDevice, 0);
    cudaMemsetAsync(pcnt, 0, N_NODES_C * sizeof(int), 0);
    cudaMemsetAsync(pstats, 0, 2 * NH * sizeof(float), 0);

    const int cvtw_tot = NLAYERS * 128 * 264 + 2 * NLAYERS * 128 * 136;
    k_cvtw<<<(cvtw_tot + 255) / 256, 256>>>(W1, W2, Wa);
    k_hist<<<(N_EDGES_C + 255) / 256, 256>>>(ei);
    k_scan<<<1, 1024>>>();
    k_fillcsr<<<(N_EDGES_C + 255) / 256, 256>>>(ei);
    k_sortperm<<<(N_NODES_C + 7) / 8, 256>>>(ei, ea);

    float* bufA = (float*)px;
    float* bufB = (float*)px2;

    for (int l = 0; l < NLAYERS; l++) {
        const float* W1l = W1 + (size_t)l * DIN * NH;
        const float* xin  = (l & 1) ? bufB : bufA;
        float*       xout = (l & 1) ? bufA : bufB;
        int is_final = (l == NLAYERS - 1);
        k_node<<<GRID_P * 2, 256, smem_node>>>(xin, l);
        k_stats<<<1184, 256>>>(xin, W1l + 256 * NH);
        k_fused<<<GRID_P, 512, smem_fused>>>(gamma + l * NH, beta + l * NH,
                                             l, b2 + l * NH,
                                             ba + l * NH,
                                             Wb + l * NH,
                                             Wm + l * NH, bm + l);
        k_agg<<<(N_NODES_C + 7) / 8, 256>>>(xin, xout, is_final, We, be, out);
    }
}